// round 1
// baseline (speedup 1.0000x reference)
#include <cuda_runtime.h>

// Problem shape (fixed by the dataset)
#define B_ 8192
#define D_ 4096
#define H_ 2048
#define K_ 512
#define LN_EPS 1e-5f

// Scratch for the hidden activation h[B, H] (64 MB). __device__ global per the
// allocation rules.
__device__ __align__(128) float g_h[(size_t)B_ * H_];

// ---------------------------------------------------------------------------
// Generic NT GEMM: C[M,N] = A[M,K] (row-major) * Bm[N,K]^T (row-major) + bias
//   EPI = 0: plain store to C0
//   EPI = 1: store to C0, C1, C2 (q_logits replicated into 3 output slots)
//   EPI = 2: sigmoid then store to C0
//   SUB_MEAN: subtract mean[k] from A elements on load (GEMM1 compound_mean)
// Tile: 128x128, K-step 8, 256 threads, 8x8 accumulators per thread.
// ---------------------------------------------------------------------------
template<int EPI, bool SUB_MEAN, bool HAS_BIAS>
__global__ void __launch_bounds__(256, 2)
gemm_nt_kernel(const float* __restrict__ A, const float* __restrict__ Bm,
               const float* __restrict__ bias, const float* __restrict__ mean,
               float* __restrict__ C0, float* __restrict__ C1,
               float* __restrict__ C2,
               int M, int N, int K)
{
    __shared__ float As[8][128];
    __shared__ float Bs[8][128];

    const int tid = threadIdx.x;
    const int m0 = blockIdx.y * 128;
    const int n0 = blockIdx.x * 128;

    // Global->shared loader mapping: one float4 of A and one of B per thread.
    const int lr = tid >> 1;          // tile row 0..127
    const int lk = (tid & 1) * 4;     // k offset 0 or 4

    // Compute mapping: 16x16 thread grid, each owns an 8x8 output micro-tile.
    const int tm = tid >> 4;          // 0..15
    const int tn = tid & 15;          // 0..15

    float acc[8][8];
#pragma unroll
    for (int i = 0; i < 8; ++i)
#pragma unroll
        for (int j = 0; j < 8; ++j) acc[i][j] = 0.f;

    const float* Ap = A  + (size_t)(m0 + lr) * K + lk;
    const float* Bp = Bm + (size_t)(n0 + lr) * K + lk;

    for (int k0 = 0; k0 < K; k0 += 8) {
        float4 av = *reinterpret_cast<const float4*>(Ap + k0);
        float4 bv = *reinterpret_cast<const float4*>(Bp + k0);
        if (SUB_MEAN) {
            const float* mp = mean + k0 + lk;
            av.x -= mp[0]; av.y -= mp[1]; av.z -= mp[2]; av.w -= mp[3];
        }
        __syncthreads();   // previous iteration's reads done
        As[lk + 0][lr] = av.x; As[lk + 1][lr] = av.y;
        As[lk + 2][lr] = av.z; As[lk + 3][lr] = av.w;
        Bs[lk + 0][lr] = bv.x; Bs[lk + 1][lr] = bv.y;
        Bs[lk + 2][lr] = bv.z; Bs[lk + 3][lr] = bv.w;
        __syncthreads();   // tile visible

#pragma unroll
        for (int kk = 0; kk < 8; ++kk) {
            float a[8], b[8];
            float4 t;
            t = *reinterpret_cast<const float4*>(&As[kk][tm * 8]);
            a[0] = t.x; a[1] = t.y; a[2] = t.z; a[3] = t.w;
            t = *reinterpret_cast<const float4*>(&As[kk][tm * 8 + 4]);
            a[4] = t.x; a[5] = t.y; a[6] = t.z; a[7] = t.w;
            t = *reinterpret_cast<const float4*>(&Bs[kk][tn * 8]);
            b[0] = t.x; b[1] = t.y; b[2] = t.z; b[3] = t.w;
            t = *reinterpret_cast<const float4*>(&Bs[kk][tn * 8 + 4]);
            b[4] = t.x; b[5] = t.y; b[6] = t.z; b[7] = t.w;
#pragma unroll
            for (int i = 0; i < 8; ++i)
#pragma unroll
                for (int j = 0; j < 8; ++j)
                    acc[i][j] += a[i] * b[j];
        }
    }

    // Epilogue
#pragma unroll
    for (int i = 0; i < 8; ++i) {
        const int row = m0 + tm * 8 + i;
        const int col = n0 + tn * 8;
        float v[8];
#pragma unroll
        for (int j = 0; j < 8; ++j) {
            float t = acc[i][j];
            if (HAS_BIAS) t += bias[col + j];
            if (EPI == 2) t = 1.f / (1.f + __expf(-t));
            v[j] = t;
        }
        const size_t off = (size_t)row * N + col;
        const float4 p0 = make_float4(v[0], v[1], v[2], v[3]);
        const float4 p1 = make_float4(v[4], v[5], v[6], v[7]);
        *reinterpret_cast<float4*>(C0 + off)     = p0;
        *reinterpret_cast<float4*>(C0 + off + 4) = p1;
        if (EPI == 1) {
            *reinterpret_cast<float4*>(C1 + off)     = p0;
            *reinterpret_cast<float4*>(C1 + off + 4) = p1;
            *reinterpret_cast<float4*>(C2 + off)     = p0;
            *reinterpret_cast<float4*>(C2 + off + 4) = p1;
        }
    }
}

// ---------------------------------------------------------------------------
// In-place LayerNorm (over H) + ReLU. One block per row, 256 threads,
// 8 elements (2 float4) per thread. H_ = 2048.
// ---------------------------------------------------------------------------
__global__ void __launch_bounds__(256)
ln_relu_kernel(float* __restrict__ h, const float* __restrict__ w,
               const float* __restrict__ b)
{
    const int row = blockIdx.x;
    const int tid = threadIdx.x;
    float4* hr = reinterpret_cast<float4*>(h + (size_t)row * H_);

    float4 v0 = hr[tid];
    float4 v1 = hr[tid + 256];

    float s  = v0.x + v0.y + v0.z + v0.w + v1.x + v1.y + v1.z + v1.w;
    float sq = v0.x * v0.x + v0.y * v0.y + v0.z * v0.z + v0.w * v0.w
             + v1.x * v1.x + v1.y * v1.y + v1.z * v1.z + v1.w * v1.w;

#pragma unroll
    for (int o = 16; o; o >>= 1) {
        s  += __shfl_xor_sync(0xffffffffu, s,  o);
        sq += __shfl_xor_sync(0xffffffffu, sq, o);
    }

    __shared__ float red[16];
    const int wid  = tid >> 5;
    const int lane = tid & 31;
    if (lane == 0) { red[wid] = s; red[8 + wid] = sq; }
    __syncthreads();

    float ts = 0.f, tq = 0.f;
#pragma unroll
    for (int i = 0; i < 8; ++i) { ts += red[i]; tq += red[8 + i]; }

    const float mu  = ts * (1.f / H_);
    const float var = tq * (1.f / H_) - mu * mu;
    const float r   = rsqrtf(var + LN_EPS);

    const float4* w4 = reinterpret_cast<const float4*>(w);
    const float4* b4 = reinterpret_cast<const float4*>(b);
    const float4 w0 = w4[tid], w1 = w4[tid + 256];
    const float4 b0 = b4[tid], b1 = b4[tid + 256];

    v0.x = fmaxf((v0.x - mu) * r * w0.x + b0.x, 0.f);
    v0.y = fmaxf((v0.y - mu) * r * w0.y + b0.y, 0.f);
    v0.z = fmaxf((v0.z - mu) * r * w0.z + b0.z, 0.f);
    v0.w = fmaxf((v0.w - mu) * r * w0.w + b0.w, 0.f);
    v1.x = fmaxf((v1.x - mu) * r * w1.x + b1.x, 0.f);
    v1.y = fmaxf((v1.y - mu) * r * w1.y + b1.y, 0.f);
    v1.z = fmaxf((v1.z - mu) * r * w1.z + b1.z, 0.f);
    v1.w = fmaxf((v1.w - mu) * r * w1.w + b1.w, 0.f);

    hr[tid]       = v0;
    hr[tid + 256] = v1;
}

// ---------------------------------------------------------------------------
// kernel_launch: 4 launches on the capture stream, no allocs, no syncs.
// Input order (metadata): x, beta, compound_mean, W1, b1, ln_w, ln_b, W2, b2
// Output layout: [q_logits | x_recon | q_logits | q_logits]
// ---------------------------------------------------------------------------
extern "C" void kernel_launch(void* const* d_in, const int* in_sizes, int n_in,
                              void* d_out, int out_size)
{
    const float* x    = (const float*)d_in[0];
    const float* beta = (const float*)d_in[1];
    const float* mean = (const float*)d_in[2];
    const float* W1   = (const float*)d_in[3];
    const float* b1   = (const float*)d_in[4];
    const float* lnw  = (const float*)d_in[5];
    const float* lnb  = (const float*)d_in[6];
    const float* W2   = (const float*)d_in[7];
    const float* b2   = (const float*)d_in[8];

    float* out = (float*)d_out;
    float* q0 = out;                                  // [B, K]
    float* xr = out + (size_t)B_ * K_;                // [B, D]
    float* q1 = xr + (size_t)B_ * D_;                 // [B, K]
    float* q2 = q1 + (size_t)B_ * K_;                 // [B, K]

    float* hbuf;
    cudaGetSymbolAddress((void**)&hbuf, g_h);

    const dim3 blk(256);

    // GEMM1: h = (x - mean) @ W1^T + b1   [8192, 2048]
    gemm_nt_kernel<0, true, true><<<dim3(H_ / 128, B_ / 128), blk>>>(
        x, W1, b1, mean, hbuf, nullptr, nullptr, B_, H_, D_);

    // LayerNorm + ReLU in place
    ln_relu_kernel<<<B_, 256>>>(hbuf, lnw, lnb);

    // GEMM2: q = h @ W2^T + b2   [8192, 512]  -> three output slots
    gemm_nt_kernel<1, false, true><<<dim3(K_ / 128, B_ / 128), blk>>>(
        hbuf, W2, b2, nullptr, q0, q1, q2, B_, K_, H_);

    // GEMM3: x_recon = sigmoid(q @ beta^T)   [8192, 4096]
    gemm_nt_kernel<2, false, false><<<dim3(D_ / 128, B_ / 128), blk>>>(
        q0, beta, nullptr, nullptr, xr, nullptr, nullptr, B_, D_, K_);
}

// round 3
// speedup vs baseline: 2.0525x; 2.0525x over previous
#include <cuda_runtime.h>
#include <cuda_bf16.h>
#include <cstdint>

#define B_ 8192
#define D_ 4096
#define H_ 2048
#define K_ 512
#define LN_EPS 1e-5f

// ---------------------------------------------------------------------------
// Scratch (device globals; runtime allocation forbidden)
// ---------------------------------------------------------------------------
__device__ __align__(256) float         g_h  [(size_t)B_ * H_];
__device__ __align__(256) __nv_bfloat16 g_xh [(size_t)B_ * D_];
__device__ __align__(256) __nv_bfloat16 g_xl [(size_t)B_ * D_];
__device__ __align__(256) __nv_bfloat16 g_hh [(size_t)B_ * H_];
__device__ __align__(256) __nv_bfloat16 g_hl [(size_t)B_ * H_];
__device__ __align__(256) __nv_bfloat16 g_qh [(size_t)B_ * K_];
__device__ __align__(256) __nv_bfloat16 g_ql [(size_t)B_ * K_];
__device__ __align__(256) __nv_bfloat16 g_w1h[(size_t)H_ * D_];
__device__ __align__(256) __nv_bfloat16 g_w1l[(size_t)H_ * D_];
__device__ __align__(256) __nv_bfloat16 g_w2h[(size_t)K_ * H_];
__device__ __align__(256) __nv_bfloat16 g_w2l[(size_t)K_ * H_];
__device__ __align__(256) __nv_bfloat16 g_bth[(size_t)D_ * K_];
__device__ __align__(256) __nv_bfloat16 g_btl[(size_t)D_ * K_];

// ---------------------------------------------------------------------------
// Low-level helpers (all base-sm_103-legal PTX: cp.async / ldmatrix / mma.sync)
// ---------------------------------------------------------------------------
__device__ __forceinline__ uint32_t smem_u32(const void* p) {
    uint32_t a;
    asm("{ .reg .u64 t; cvta.to.shared.u64 t, %1; cvt.u32.u64 %0, t; }"
        : "=r"(a) : "l"(p));
    return a;
}

__device__ __forceinline__ void cpa16(uint32_t dst, const void* src) {
    asm volatile("cp.async.cg.shared.global [%0], [%1], 16;"
                 :: "r"(dst), "l"(src) : "memory");
}
#define CP_COMMIT() asm volatile("cp.async.commit_group;" ::: "memory")
#define CP_WAIT2()  asm volatile("cp.async.wait_group 2;" ::: "memory")

#define LDM_X4(r0, r1, r2, r3, addr)                                          \
    asm volatile("ldmatrix.sync.aligned.m8n8.x4.shared.b16 {%0,%1,%2,%3}, [%4];" \
                 : "=r"(r0), "=r"(r1), "=r"(r2), "=r"(r3) : "r"(addr))

__device__ __forceinline__ void mma_bf16(float* c, const uint32_t* a,
                                         uint32_t b0, uint32_t b1) {
    asm volatile(
        "mma.sync.aligned.m16n8k16.row.col.f32.bf16.bf16.f32 "
        "{%0,%1,%2,%3}, {%4,%5,%6,%7}, {%8,%9}, {%0,%1,%2,%3};"
        : "+f"(c[0]), "+f"(c[1]), "+f"(c[2]), "+f"(c[3])
        : "r"(a[0]), "r"(a[1]), "r"(a[2]), "r"(a[3]), "r"(b0), "r"(b1));
}

// ---------------------------------------------------------------------------
// SMEM layout per pipeline stage (K-chunk = 32 bf16, rows padded to 40 elems
// = 80B for conflict-free ldmatrix):
//   Ah[128][40]  @ 0        (10240 B)
//   Al[128][40]  @ 10240
//   Bh[128][40]  @ 20480
//   Bl[128][40]  @ 30720
// Stage stride 40960 B, 3 stages = 122880 B.
// ---------------------------------------------------------------------------
#define AH_OFF 0
#define AL_OFF 10240
#define BH_OFF 20480
#define BL_OFF 30720
#define STG    40960
#define SMEM_TOTAL (3 * STG)
#define ROWB   80   // padded row bytes

__device__ __forceinline__ void load_stage(uint32_t stb,
    const __nv_bfloat16* __restrict__ Ah, const __nv_bfloat16* __restrict__ Al,
    const __nv_bfloat16* __restrict__ Bh, const __nv_bfloat16* __restrict__ Bl,
    int m0, int n0, int k0, int K, int tid)
{
    // 128 rows x 64B per tile = 512 x 16B chunks; 256 threads -> each thread
    // copies 2 contiguous 16B chunks per tile.
    const int r = tid >> 1;              // 0..127
    const int c = (tid & 1) * 2;         // chunk 0 or 2 (covers c, c+1)
    const size_t ga = (size_t)(m0 + r) * K + k0 + c * 8;
    const size_t gb = (size_t)(n0 + r) * K + k0 + c * 8;
    const uint32_t so = (uint32_t)(r * ROWB + c * 16);

    cpa16(stb + AH_OFF + so,      Ah + ga);
    cpa16(stb + AH_OFF + so + 16, Ah + ga + 8);
    cpa16(stb + AL_OFF + so,      Al + ga);
    cpa16(stb + AL_OFF + so + 16, Al + ga + 8);
    cpa16(stb + BH_OFF + so,      Bh + gb);
    cpa16(stb + BH_OFF + so + 16, Bh + gb + 8);
    cpa16(stb + BL_OFF + so,      Bl + gb);
    cpa16(stb + BL_OFF + so + 16, Bl + gb + 8);
}

// ---------------------------------------------------------------------------
// Split-bf16 tensor-core GEMM: C[128,128] tile, A[M,K] & B[N,K] row-major
// (hi/lo bf16 pairs). D = Ah*Bh + Ah*Bl + Al*Bh (fp32 accum via mma.sync).
// 8 warps; warp tile 32(M) x 64(N); m16n8k16 HMMA.
//   EPI 0: +bias -> C0                  (GEMM1 -> h, fp32)
//   EPI 1: +bias -> C0,C1,C2 + bf16 split -> Oh/Ol   (GEMM2 -> q)
//   EPI 2: sigmoid -> C0                (GEMM3 -> x_recon)
// ---------------------------------------------------------------------------
template<int EPI>
__global__ void __launch_bounds__(256, 1)
gemm_mma(const __nv_bfloat16* __restrict__ Ah, const __nv_bfloat16* __restrict__ Al,
         const __nv_bfloat16* __restrict__ Bh, const __nv_bfloat16* __restrict__ Bl,
         const float* __restrict__ bias,
         float* __restrict__ C0, float* __restrict__ C1, float* __restrict__ C2,
         __nv_bfloat16* __restrict__ Oh, __nv_bfloat16* __restrict__ Ol,
         int N, int K)
{
    extern __shared__ char smem[];
    const uint32_t sb = smem_u32(smem);

    const int tid  = threadIdx.x;
    const int lane = tid & 31;
    const int wid  = tid >> 5;
    const int wm   = wid & 3;        // warp M index (0..3) -> 32-row slab
    const int wn   = wid >> 2;       // warp N index (0..1) -> 64-col slab
    const int m0 = blockIdx.y * 128;
    const int n0 = blockIdx.x * 128;
    const int NC = K >> 5;           // K-chunks of 32

    const int lrow  = lane & 15;
    const int lcolb = ((lane >> 4) << 3) * 2;   // 0 or 16 bytes (8 elems)

    float acc[2][8][4];
#pragma unroll
    for (int m = 0; m < 2; ++m)
#pragma unroll
        for (int n = 0; n < 8; ++n)
#pragma unroll
            for (int j = 0; j < 4; ++j) acc[m][n][j] = 0.f;

    // prologue: chunks 0,1 -> stages 0,1
    load_stage(sb,       Ah, Al, Bh, Bl, m0, n0, 0,  K, tid); CP_COMMIT();
    load_stage(sb + STG, Ah, Al, Bh, Bl, m0, n0, 32, K, tid); CP_COMMIT();

    uint32_t stg_idx = 0;
    for (int c = 0; c < NC; ++c) {
        if (c + 2 < NC) {
            uint32_t ls = stg_idx + 2; if (ls >= 3) ls -= 3;
            load_stage(sb + ls * STG, Ah, Al, Bh, Bl, m0, n0, (c + 2) << 5, K, tid);
        }
        CP_COMMIT();
        CP_WAIT2();
        __syncthreads();

        const uint32_t stb = sb + stg_idx * STG;
        const uint32_t abase = stb + (wm * 32 + lrow) * ROWB + lcolb;
        const uint32_t bbase = stb + BH_OFF + (wn * 64 + lrow) * ROWB + lcolb;

#pragma unroll
        for (int kk = 0; kk < 2; ++kk) {
            const uint32_t ko = kk * 32;   // 16 elems = 32 bytes
            uint32_t ah[2][4], al[2][4], bh[4][4], bl[4][4];
#pragma unroll
            for (int m = 0; m < 2; ++m) {
                const uint32_t ao = abase + m * 16 * ROWB + ko;
                LDM_X4(ah[m][0], ah[m][1], ah[m][2], ah[m][3], ao + AH_OFF);
                LDM_X4(al[m][0], al[m][1], al[m][2], al[m][3], ao + AL_OFF);
            }
#pragma unroll
            for (int nt = 0; nt < 4; ++nt) {
                const uint32_t bo = bbase + nt * 16 * ROWB + ko;
                LDM_X4(bh[nt][0], bh[nt][1], bh[nt][2], bh[nt][3], bo);
                LDM_X4(bl[nt][0], bl[nt][1], bl[nt][2], bl[nt][3], bo + (BL_OFF - BH_OFF));
            }
#pragma unroll
            for (int m = 0; m < 2; ++m)
#pragma unroll
                for (int nt = 0; nt < 4; ++nt) {
                    // hi*hi
                    mma_bf16(acc[m][2 * nt],     ah[m], bh[nt][0], bh[nt][2]);
                    mma_bf16(acc[m][2 * nt + 1], ah[m], bh[nt][1], bh[nt][3]);
                    // hi*lo
                    mma_bf16(acc[m][2 * nt],     ah[m], bl[nt][0], bl[nt][2]);
                    mma_bf16(acc[m][2 * nt + 1], ah[m], bl[nt][1], bl[nt][3]);
                    // lo*hi
                    mma_bf16(acc[m][2 * nt],     al[m], bh[nt][0], bh[nt][2]);
                    mma_bf16(acc[m][2 * nt + 1], al[m], bh[nt][1], bh[nt][3]);
                }
        }
        __syncthreads();
        ++stg_idx; if (stg_idx == 3) stg_idx = 0;
    }

    // ------------------------------ epilogue ------------------------------
    const int rbase = m0 + wm * 32 + (lane >> 2);
    const int cbase = n0 + wn * 64 + 2 * (lane & 3);
#pragma unroll
    for (int m = 0; m < 2; ++m) {
        const int row = rbase + m * 16;
#pragma unroll
        for (int n = 0; n < 8; ++n) {
            const int col = cbase + n * 8;
            float v[4] = {acc[m][n][0], acc[m][n][1], acc[m][n][2], acc[m][n][3]};
            if (EPI == 0 || EPI == 1) {
                const float bb0 = bias[col], bb1 = bias[col + 1];
                v[0] += bb0; v[1] += bb1; v[2] += bb0; v[3] += bb1;
            }
            if (EPI == 2) {
#pragma unroll
                for (int j = 0; j < 4; ++j) v[j] = 1.f / (1.f + __expf(-v[j]));
            }
            const size_t o0 = (size_t)row * N + col;
            const size_t o1 = (size_t)(row + 8) * N + col;
            *reinterpret_cast<float2*>(C0 + o0) = make_float2(v[0], v[1]);
            *reinterpret_cast<float2*>(C0 + o1) = make_float2(v[2], v[3]);
            if (EPI == 1) {
                *reinterpret_cast<float2*>(C1 + o0) = make_float2(v[0], v[1]);
                *reinterpret_cast<float2*>(C1 + o1) = make_float2(v[2], v[3]);
                *reinterpret_cast<float2*>(C2 + o0) = make_float2(v[0], v[1]);
                *reinterpret_cast<float2*>(C2 + o1) = make_float2(v[2], v[3]);
                const size_t oo[4] = {o0, o0 + 1, o1, o1 + 1};
#pragma unroll
                for (int j = 0; j < 4; ++j) {
                    __nv_bfloat16 hv = __float2bfloat16(v[j]);
                    Oh[oo[j]] = hv;
                    Ol[oo[j]] = __float2bfloat16(v[j] - __bfloat162float(hv));
                }
            }
        }
    }
}

// ---------------------------------------------------------------------------
// fp32 -> bf16 hi/lo split (optionally subtracting periodic mean vector)
// ---------------------------------------------------------------------------
__global__ void __launch_bounds__(256)
split_kernel(const float* __restrict__ src, const float* __restrict__ mean,
             __nv_bfloat16* __restrict__ hi, __nv_bfloat16* __restrict__ lo,
             int dmask, int n4)
{
    int i = blockIdx.x * 256 + threadIdx.x;
    if (i >= n4) return;
    float4 v = reinterpret_cast<const float4*>(src)[i];
    int e = i * 4;
    if (mean) {
        v.x -= mean[(e + 0) & dmask]; v.y -= mean[(e + 1) & dmask];
        v.z -= mean[(e + 2) & dmask]; v.w -= mean[(e + 3) & dmask];
    }
    float a[4] = {v.x, v.y, v.z, v.w};
#pragma unroll
    for (int j = 0; j < 4; ++j) {
        __nv_bfloat16 h = __float2bfloat16(a[j]);
        hi[e + j] = h;
        lo[e + j] = __float2bfloat16(a[j] - __bfloat162float(h));
    }
}

// ---------------------------------------------------------------------------
// LayerNorm + ReLU over H, fp32 in -> bf16 hi/lo out
// ---------------------------------------------------------------------------
__global__ void __launch_bounds__(256)
ln_relu_split(const float* __restrict__ h, const float* __restrict__ w,
              const float* __restrict__ b,
              __nv_bfloat16* __restrict__ oh, __nv_bfloat16* __restrict__ ol)
{
    const int row = blockIdx.x;
    const int tid = threadIdx.x;
    const float4* hr = reinterpret_cast<const float4*>(h + (size_t)row * H_);

    float4 v0 = hr[tid];
    float4 v1 = hr[tid + 256];

    float s  = v0.x + v0.y + v0.z + v0.w + v1.x + v1.y + v1.z + v1.w;
    float sq = v0.x*v0.x + v0.y*v0.y + v0.z*v0.z + v0.w*v0.w
             + v1.x*v1.x + v1.y*v1.y + v1.z*v1.z + v1.w*v1.w;
#pragma unroll
    for (int o = 16; o; o >>= 1) {
        s  += __shfl_xor_sync(0xffffffffu, s,  o);
        sq += __shfl_xor_sync(0xffffffffu, sq, o);
    }
    __shared__ float red[16];
    const int wd = tid >> 5, lane = tid & 31;
    if (lane == 0) { red[wd] = s; red[8 + wd] = sq; }
    __syncthreads();
    float ts = 0.f, tq = 0.f;
#pragma unroll
    for (int i = 0; i < 8; ++i) { ts += red[i]; tq += red[8 + i]; }

    const float mu  = ts * (1.f / H_);
    const float var = tq * (1.f / H_) - mu * mu;
    const float rr  = rsqrtf(var + LN_EPS);

    const float4* w4 = reinterpret_cast<const float4*>(w);
    const float4* b4 = reinterpret_cast<const float4*>(b);
    const float4 w0 = w4[tid], w1 = w4[tid + 256];
    const float4 b0 = b4[tid], b1 = b4[tid + 256];

    float out[8];
    out[0] = fmaxf((v0.x - mu) * rr * w0.x + b0.x, 0.f);
    out[1] = fmaxf((v0.y - mu) * rr * w0.y + b0.y, 0.f);
    out[2] = fmaxf((v0.z - mu) * rr * w0.z + b0.z, 0.f);
    out[3] = fmaxf((v0.w - mu) * rr * w0.w + b0.w, 0.f);
    out[4] = fmaxf((v1.x - mu) * rr * w1.x + b1.x, 0.f);
    out[5] = fmaxf((v1.y - mu) * rr * w1.y + b1.y, 0.f);
    out[6] = fmaxf((v1.z - mu) * rr * w1.z + b1.z, 0.f);
    out[7] = fmaxf((v1.w - mu) * rr * w1.w + b1.w, 0.f);

    const size_t base0 = (size_t)row * H_ + (size_t)tid * 4;
    const size_t base1 = base0 + 1024;
#pragma unroll
    for (int j = 0; j < 4; ++j) {
        __nv_bfloat16 hv = __float2bfloat16(out[j]);
        oh[base0 + j] = hv;
        ol[base0 + j] = __float2bfloat16(out[j] - __bfloat162float(hv));
        __nv_bfloat16 hv2 = __float2bfloat16(out[4 + j]);
        oh[base1 + j] = hv2;
        ol[base1 + j] = __float2bfloat16(out[4 + j] - __bfloat162float(hv2));
    }
}

// ---------------------------------------------------------------------------
// kernel_launch
// ---------------------------------------------------------------------------
extern "C" void kernel_launch(void* const* d_in, const int* in_sizes, int n_in,
                              void* d_out, int out_size)
{
    const float* x    = (const float*)d_in[0];
    const float* beta = (const float*)d_in[1];
    const float* mean = (const float*)d_in[2];
    const float* W1   = (const float*)d_in[3];
    const float* b1   = (const float*)d_in[4];
    const float* lnw  = (const float*)d_in[5];
    const float* lnb  = (const float*)d_in[6];
    const float* W2   = (const float*)d_in[7];
    const float* b2   = (const float*)d_in[8];

    float* out = (float*)d_out;
    float* q0 = out;                        // [B, K]
    float* xr = out + (size_t)B_ * K_;      // [B, D]
    float* q1 = xr + (size_t)B_ * D_;       // [B, K]
    float* q2 = q1 + (size_t)B_ * K_;       // [B, K]

    void *p_h, *p_xh, *p_xl, *p_hh, *p_hl, *p_qh, *p_ql;
    void *p_w1h, *p_w1l, *p_w2h, *p_w2l, *p_bth, *p_btl;
    cudaGetSymbolAddress(&p_h,  g_h);
    cudaGetSymbolAddress(&p_xh, g_xh);  cudaGetSymbolAddress(&p_xl, g_xl);
    cudaGetSymbolAddress(&p_hh, g_hh);  cudaGetSymbolAddress(&p_hl, g_hl);
    cudaGetSymbolAddress(&p_qh, g_qh);  cudaGetSymbolAddress(&p_ql, g_ql);
    cudaGetSymbolAddress(&p_w1h, g_w1h); cudaGetSymbolAddress(&p_w1l, g_w1l);
    cudaGetSymbolAddress(&p_w2h, g_w2h); cudaGetSymbolAddress(&p_w2l, g_w2l);
    cudaGetSymbolAddress(&p_bth, g_bth); cudaGetSymbolAddress(&p_btl, g_btl);

    float* hbuf = (float*)p_h;
    __nv_bfloat16 *xh = (__nv_bfloat16*)p_xh, *xl = (__nv_bfloat16*)p_xl;
    __nv_bfloat16 *hh = (__nv_bfloat16*)p_hh, *hl = (__nv_bfloat16*)p_hl;
    __nv_bfloat16 *qh = (__nv_bfloat16*)p_qh, *ql = (__nv_bfloat16*)p_ql;
    __nv_bfloat16 *w1h = (__nv_bfloat16*)p_w1h, *w1l = (__nv_bfloat16*)p_w1l;
    __nv_bfloat16 *w2h = (__nv_bfloat16*)p_w2h, *w2l = (__nv_bfloat16*)p_w2l;
    __nv_bfloat16 *bth = (__nv_bfloat16*)p_bth, *btl = (__nv_bfloat16*)p_btl;

    cudaFuncSetAttribute(gemm_mma<0>, cudaFuncAttributeMaxDynamicSharedMemorySize, SMEM_TOTAL);
    cudaFuncSetAttribute(gemm_mma<1>, cudaFuncAttributeMaxDynamicSharedMemorySize, SMEM_TOTAL);
    cudaFuncSetAttribute(gemm_mma<2>, cudaFuncAttributeMaxDynamicSharedMemorySize, SMEM_TOTAL);

    // hi/lo splits
    split_kernel<<<(B_ * D_ / 4) / 256, 256>>>(x,    mean,    xh,  xl,  D_ - 1, B_ * D_ / 4);
    split_kernel<<<(H_ * D_ / 4) / 256, 256>>>(W1,   nullptr, w1h, w1l, 0,      H_ * D_ / 4);
    split_kernel<<<(K_ * H_ / 4) / 256, 256>>>(W2,   nullptr, w2h, w2l, 0,      K_ * H_ / 4);
    split_kernel<<<(D_ * K_ / 4) / 256, 256>>>(beta, nullptr, bth, btl, 0,      D_ * K_ / 4);

    // GEMM1: h = (x-mean) @ W1^T + b1   [8192, 2048], K=4096
    gemm_mma<0><<<dim3(H_ / 128, B_ / 128), 256, SMEM_TOTAL>>>(
        xh, xl, w1h, w1l, b1, hbuf, nullptr, nullptr, nullptr, nullptr, H_, D_);

    // LayerNorm + ReLU -> bf16 split
    ln_relu_split<<<B_, 256>>>(hbuf, lnw, lnb, hh, hl);

    // GEMM2: q = h @ W2^T + b2   [8192, 512], K=2048  -> q0/q1/q2 + split
    gemm_mma<1><<<dim3(K_ / 128, B_ / 128), 256, SMEM_TOTAL>>>(
        hh, hl, w2h, w2l, b2, q0, q1, q2, qh, ql, K_, H_);

    // GEMM3: x_recon = sigmoid(q @ beta^T)   [8192, 4096], K=512
    gemm_mma<2><<<dim3(D_ / 128, B_ / 128), 256, SMEM_TOTAL>>>(
        qh, ql, bth, btl, nullptr, xr, nullptr, nullptr, nullptr, nullptr, D_, K_);
}

// round 4
// speedup vs baseline: 2.3801x; 1.1596x over previous
#include <cuda_runtime.h>
#include <cuda_bf16.h>
#include <cstdint>

#define B_ 8192
#define D_ 4096
#define H_ 2048
#define K_ 512
#define LN_EPS 1e-5f

// ---------------------------------------------------------------------------
// Scratch (device globals; runtime allocation forbidden)
// ---------------------------------------------------------------------------
__device__ __align__(256) float         g_h  [(size_t)B_ * H_];
__device__ __align__(256) __nv_bfloat16 g_xh [(size_t)B_ * D_];
__device__ __align__(256) __nv_bfloat16 g_xl [(size_t)B_ * D_];
__device__ __align__(256) __nv_bfloat16 g_hh [(size_t)B_ * H_];
__device__ __align__(256) __nv_bfloat16 g_hl [(size_t)B_ * H_];
__device__ __align__(256) __nv_bfloat16 g_qh [(size_t)B_ * K_];
__device__ __align__(256) __nv_bfloat16 g_ql [(size_t)B_ * K_];
__device__ __align__(256) __nv_bfloat16 g_w1h[(size_t)H_ * D_];
__device__ __align__(256) __nv_bfloat16 g_w1l[(size_t)H_ * D_];
__device__ __align__(256) __nv_bfloat16 g_w2h[(size_t)K_ * H_];
__device__ __align__(256) __nv_bfloat16 g_w2l[(size_t)K_ * H_];
__device__ __align__(256) __nv_bfloat16 g_bth[(size_t)D_ * K_];
__device__ __align__(256) __nv_bfloat16 g_btl[(size_t)D_ * K_];

// ---------------------------------------------------------------------------
// Low-level helpers (base sm_103-legal: cp.async / ldmatrix / mma.sync)
// ---------------------------------------------------------------------------
__device__ __forceinline__ uint32_t smem_u32(const void* p) {
    uint32_t a;
    asm("{ .reg .u64 t; cvta.to.shared.u64 t, %1; cvt.u32.u64 %0, t; }"
        : "=r"(a) : "l"(p));
    return a;
}

__device__ __forceinline__ void cpa16(uint32_t dst, const void* src) {
    asm volatile("cp.async.cg.shared.global [%0], [%1], 16;"
                 :: "r"(dst), "l"(src) : "memory");
}
#define CP_COMMIT() asm volatile("cp.async.commit_group;" ::: "memory")
#define CP_WAIT2()  asm volatile("cp.async.wait_group 2;" ::: "memory")

#define LDM_X4(r0, r1, r2, r3, addr)                                          \
    asm volatile("ldmatrix.sync.aligned.m8n8.x4.shared.b16 {%0,%1,%2,%3}, [%4];" \
                 : "=r"(r0), "=r"(r1), "=r"(r2), "=r"(r3) : "r"(addr))

__device__ __forceinline__ void mma_bf16(float* c, const uint32_t* a,
                                         uint32_t b0, uint32_t b1) {
    asm volatile(
        "mma.sync.aligned.m16n8k16.row.col.f32.bf16.bf16.f32 "
        "{%0,%1,%2,%3}, {%4,%5,%6,%7}, {%8,%9}, {%0,%1,%2,%3};"
        : "+f"(c[0]), "+f"(c[1]), "+f"(c[2]), "+f"(c[3])
        : "r"(a[0]), "r"(a[1]), "r"(a[2]), "r"(a[3]), "r"(b0), "r"(b1));
}

// ---------------------------------------------------------------------------
// SMEM layout per pipeline stage. K-chunk = 64 bf16 (128B) per row, rows
// padded to 72 elems (144B): bank stride 144/4=36 ≡ 4 (mod 32) -> the 8
// ldmatrix row addresses land in distinct bank groups (conflict-free).
//   Ah[128][72] @ 0      (18432 B)
//   Al[128][72] @ 18432
//   Bh[128][72] @ 36864
//   Bl[128][72] @ 55296
// Stage stride 73728 B, 3 stages = 221184 B total dynamic SMEM.
// ---------------------------------------------------------------------------
#define ROWB   144
#define AH_OFF 0
#define AL_OFF 18432
#define BH_OFF 36864
#define BL_OFF 55296
#define STG    73728
#define SMEM_TOTAL (3 * STG)

__device__ __forceinline__ void load_stage(uint32_t stb,
    const __nv_bfloat16* __restrict__ Ah, const __nv_bfloat16* __restrict__ Al,
    const __nv_bfloat16* __restrict__ Bh, const __nv_bfloat16* __restrict__ Bl,
    int m0, int n0, int k0, int K, int tid)
{
    // Each tile: 128 rows x 128B = 1024 x 16B chunks; 256 threads -> 4 chunks
    // per thread per tile.
#pragma unroll
    for (int i = 0; i < 4; ++i) {
        const int idx = tid + i * 256;
        const int r = idx >> 3;            // 0..127
        const int c = idx & 7;             // 16B chunk 0..7
        const size_t ga = (size_t)(m0 + r) * K + k0 + c * 8;
        const size_t gb = (size_t)(n0 + r) * K + k0 + c * 8;
        const uint32_t so = (uint32_t)(r * ROWB + c * 16);
        cpa16(stb + AH_OFF + so, Ah + ga);
        cpa16(stb + AL_OFF + so, Al + ga);
        cpa16(stb + BH_OFF + so, Bh + gb);
        cpa16(stb + BL_OFF + so, Bl + gb);
    }
}

// ---------------------------------------------------------------------------
// Split-bf16 tensor-core GEMM: C[128,128] CTA tile, A[M,K] & B[N,K] row-major
// hi/lo bf16 pairs. D = Ah*Bh + Ah*Bl + Al*Bh (fp32 accum, m16n8k16 HMMA).
// 8 warps; warp tile 32(M) x 64(N).
//   EPI 0: +bias -> C0
//   EPI 1: +bias -> C0,C1,C2 + bf16 split -> Oh/Ol
//   EPI 2: sigmoid -> C0
// ---------------------------------------------------------------------------
template<int EPI>
__global__ void __launch_bounds__(256, 1)
gemm_mma(const __nv_bfloat16* __restrict__ Ah, const __nv_bfloat16* __restrict__ Al,
         const __nv_bfloat16* __restrict__ Bh, const __nv_bfloat16* __restrict__ Bl,
         const float* __restrict__ bias,
         float* __restrict__ C0, float* __restrict__ C1, float* __restrict__ C2,
         __nv_bfloat16* __restrict__ Oh, __nv_bfloat16* __restrict__ Ol,
         int N, int K)
{
    extern __shared__ char smem[];
    const uint32_t sb = smem_u32(smem);

    const int tid  = threadIdx.x;
    const int lane = tid & 31;
    const int wid  = tid >> 5;
    const int wm   = wid & 3;        // warp M index -> 32-row slab
    const int wn   = wid >> 2;       // warp N index -> 64-col slab
    const int m0 = blockIdx.y * 128;
    const int n0 = blockIdx.x * 128;
    const int NC = K >> 6;           // K-chunks of 64

    const int lrow  = lane & 15;
    const int lcolb = ((lane >> 4) << 4);   // 0 or 16 bytes

    float acc[2][8][4];
#pragma unroll
    for (int m = 0; m < 2; ++m)
#pragma unroll
        for (int n = 0; n < 8; ++n)
#pragma unroll
            for (int j = 0; j < 4; ++j) acc[m][n][j] = 0.f;

    // prologue: chunks 0,1 -> stages 0,1
    load_stage(sb,       Ah, Al, Bh, Bl, m0, n0, 0,  K, tid); CP_COMMIT();
    load_stage(sb + STG, Ah, Al, Bh, Bl, m0, n0, 64, K, tid); CP_COMMIT();

    uint32_t stg_idx = 0;
    for (int c = 0; c < NC; ++c) {
        if (c + 2 < NC) {
            uint32_t ls = stg_idx + 2; if (ls >= 3) ls -= 3;
            load_stage(sb + ls * STG, Ah, Al, Bh, Bl, m0, n0, (c + 2) << 6, K, tid);
        }
        CP_COMMIT();
        CP_WAIT2();
        __syncthreads();

        const uint32_t stb = sb + stg_idx * STG;
        const uint32_t abase = stb + (wm * 32 + lrow) * ROWB + lcolb;
        const uint32_t bbase = stb + BH_OFF + (wn * 64 + lrow) * ROWB + lcolb;

#pragma unroll
        for (int kk = 0; kk < 4; ++kk) {
            const uint32_t ko = kk * 32;   // 16 elems = 32 bytes
            uint32_t ah[2][4], al[2][4], bh[4][4], bl[4][4];
#pragma unroll
            for (int m = 0; m < 2; ++m) {
                const uint32_t ao = abase + m * 16 * ROWB + ko;
                LDM_X4(ah[m][0], ah[m][1], ah[m][2], ah[m][3], ao + AH_OFF);
                LDM_X4(al[m][0], al[m][1], al[m][2], al[m][3], ao + AL_OFF);
            }
#pragma unroll
            for (int nt = 0; nt < 4; ++nt) {
                const uint32_t bo = bbase + nt * 16 * ROWB + ko;
                LDM_X4(bh[nt][0], bh[nt][1], bh[nt][2], bh[nt][3], bo);
                LDM_X4(bl[nt][0], bl[nt][1], bl[nt][2], bl[nt][3], bo + (BL_OFF - BH_OFF));
            }
#pragma unroll
            for (int m = 0; m < 2; ++m)
#pragma unroll
                for (int nt = 0; nt < 4; ++nt) {
                    mma_bf16(acc[m][2 * nt],     ah[m], bh[nt][0], bh[nt][2]);
                    mma_bf16(acc[m][2 * nt + 1], ah[m], bh[nt][1], bh[nt][3]);
                    mma_bf16(acc[m][2 * nt],     ah[m], bl[nt][0], bl[nt][2]);
                    mma_bf16(acc[m][2 * nt + 1], ah[m], bl[nt][1], bl[nt][3]);
                    mma_bf16(acc[m][2 * nt],     al[m], bh[nt][0], bh[nt][2]);
                    mma_bf16(acc[m][2 * nt + 1], al[m], bh[nt][1], bh[nt][3]);
                }
        }
        __syncthreads();
        ++stg_idx; if (stg_idx == 3) stg_idx = 0;
    }

    // ------------------------------ epilogue ------------------------------
    const int rbase = m0 + wm * 32 + (lane >> 2);
    const int cbase = n0 + wn * 64 + 2 * (lane & 3);
#pragma unroll
    for (int m = 0; m < 2; ++m) {
        const int row = rbase + m * 16;
#pragma unroll
        for (int n = 0; n < 8; ++n) {
            const int col = cbase + n * 8;
            float v[4] = {acc[m][n][0], acc[m][n][1], acc[m][n][2], acc[m][n][3]};
            if (EPI == 0 || EPI == 1) {
                const float bb0 = bias[col], bb1 = bias[col + 1];
                v[0] += bb0; v[1] += bb1; v[2] += bb0; v[3] += bb1;
            }
            if (EPI == 2) {
#pragma unroll
                for (int j = 0; j < 4; ++j) v[j] = 1.f / (1.f + __expf(-v[j]));
            }
            const size_t o0 = (size_t)row * N + col;
            const size_t o1 = (size_t)(row + 8) * N + col;
            *reinterpret_cast<float2*>(C0 + o0) = make_float2(v[0], v[1]);
            *reinterpret_cast<float2*>(C0 + o1) = make_float2(v[2], v[3]);
            if (EPI == 1) {
                *reinterpret_cast<float2*>(C1 + o0) = make_float2(v[0], v[1]);
                *reinterpret_cast<float2*>(C1 + o1) = make_float2(v[2], v[3]);
                *reinterpret_cast<float2*>(C2 + o0) = make_float2(v[0], v[1]);
                *reinterpret_cast<float2*>(C2 + o1) = make_float2(v[2], v[3]);
                const size_t oo[4] = {o0, o0 + 1, o1, o1 + 1};
#pragma unroll
                for (int j = 0; j < 4; ++j) {
                    __nv_bfloat16 hv = __float2bfloat16(v[j]);
                    Oh[oo[j]] = hv;
                    Ol[oo[j]] = __float2bfloat16(v[j] - __bfloat162float(hv));
                }
            }
        }
    }
}

// ---------------------------------------------------------------------------
// fp32 -> bf16 hi/lo split (optionally subtracting periodic mean vector)
// ---------------------------------------------------------------------------
__global__ void __launch_bounds__(256)
split_kernel(const float* __restrict__ src, const float* __restrict__ mean,
             __nv_bfloat16* __restrict__ hi, __nv_bfloat16* __restrict__ lo,
             int dmask, int n4)
{
    int i = blockIdx.x * 256 + threadIdx.x;
    if (i >= n4) return;
    float4 v = reinterpret_cast<const float4*>(src)[i];
    int e = i * 4;
    if (mean) {
        v.x -= mean[(e + 0) & dmask]; v.y -= mean[(e + 1) & dmask];
        v.z -= mean[(e + 2) & dmask]; v.w -= mean[(e + 3) & dmask];
    }
    float a[4] = {v.x, v.y, v.z, v.w};
#pragma unroll
    for (int j = 0; j < 4; ++j) {
        __nv_bfloat16 h = __float2bfloat16(a[j]);
        hi[e + j] = h;
        lo[e + j] = __float2bfloat16(a[j] - __bfloat162float(h));
    }
}

// ---------------------------------------------------------------------------
// LayerNorm + ReLU over H, fp32 in -> bf16 hi/lo out
// ---------------------------------------------------------------------------
__global__ void __launch_bounds__(256)
ln_relu_split(const float* __restrict__ h, const float* __restrict__ w,
              const float* __restrict__ b,
              __nv_bfloat16* __restrict__ oh, __nv_bfloat16* __restrict__ ol)
{
    const int row = blockIdx.x;
    const int tid = threadIdx.x;
    const float4* hr = reinterpret_cast<const float4*>(h + (size_t)row * H_);

    float4 v0 = hr[tid];
    float4 v1 = hr[tid + 256];

    float s  = v0.x + v0.y + v0.z + v0.w + v1.x + v1.y + v1.z + v1.w;
    float sq = v0.x*v0.x + v0.y*v0.y + v0.z*v0.z + v0.w*v0.w
             + v1.x*v1.x + v1.y*v1.y + v1.z*v1.z + v1.w*v1.w;
#pragma unroll
    for (int o = 16; o; o >>= 1) {
        s  += __shfl_xor_sync(0xffffffffu, s,  o);
        sq += __shfl_xor_sync(0xffffffffu, sq, o);
    }
    __shared__ float red[16];
    const int wd = tid >> 5, lane = tid & 31;
    if (lane == 0) { red[wd] = s; red[8 + wd] = sq; }
    __syncthreads();
    float ts = 0.f, tq = 0.f;
#pragma unroll
    for (int i = 0; i < 8; ++i) { ts += red[i]; tq += red[8 + i]; }

    const float mu  = ts * (1.f / H_);
    const float var = tq * (1.f / H_) - mu * mu;
    const float rr  = rsqrtf(var + LN_EPS);

    const float4* w4 = reinterpret_cast<const float4*>(w);
    const float4* b4 = reinterpret_cast<const float4*>(b);
    const float4 w0 = w4[tid], w1 = w4[tid + 256];
    const float4 b0 = b4[tid], b1 = b4[tid + 256];

    float out[8];
    out[0] = fmaxf((v0.x - mu) * rr * w0.x + b0.x, 0.f);
    out[1] = fmaxf((v0.y - mu) * rr * w0.y + b0.y, 0.f);
    out[2] = fmaxf((v0.z - mu) * rr * w0.z + b0.z, 0.f);
    out[3] = fmaxf((v0.w - mu) * rr * w0.w + b0.w, 0.f);
    out[4] = fmaxf((v1.x - mu) * rr * w1.x + b1.x, 0.f);
    out[5] = fmaxf((v1.y - mu) * rr * w1.y + b1.y, 0.f);
    out[6] = fmaxf((v1.z - mu) * rr * w1.z + b1.z, 0.f);
    out[7] = fmaxf((v1.w - mu) * rr * w1.w + b1.w, 0.f);

    const size_t base0 = (size_t)row * H_ + (size_t)tid * 4;
    const size_t base1 = base0 + 1024;
#pragma unroll
    for (int j = 0; j < 4; ++j) {
        __nv_bfloat16 hv = __float2bfloat16(out[j]);
        oh[base0 + j] = hv;
        ol[base0 + j] = __float2bfloat16(out[j] - __bfloat162float(hv));
        __nv_bfloat16 hv2 = __float2bfloat16(out[4 + j]);
        oh[base1 + j] = hv2;
        ol[base1 + j] = __float2bfloat16(out[4 + j] - __bfloat162float(hv2));
    }
}

// ---------------------------------------------------------------------------
// kernel_launch
// ---------------------------------------------------------------------------
extern "C" void kernel_launch(void* const* d_in, const int* in_sizes, int n_in,
                              void* d_out, int out_size)
{
    const float* x    = (const float*)d_in[0];
    const float* beta = (const float*)d_in[1];
    const float* mean = (const float*)d_in[2];
    const float* W1   = (const float*)d_in[3];
    const float* b1   = (const float*)d_in[4];
    const float* lnw  = (const float*)d_in[5];
    const float* lnb  = (const float*)d_in[6];
    const float* W2   = (const float*)d_in[7];
    const float* b2   = (const float*)d_in[8];

    float* out = (float*)d_out;
    float* q0 = out;                        // [B, K]
    float* xr = out + (size_t)B_ * K_;      // [B, D]
    float* q1 = xr + (size_t)B_ * D_;       // [B, K]
    float* q2 = q1 + (size_t)B_ * K_;       // [B, K]

    void *p_h, *p_xh, *p_xl, *p_hh, *p_hl, *p_qh, *p_ql;
    void *p_w1h, *p_w1l, *p_w2h, *p_w2l, *p_bth, *p_btl;
    cudaGetSymbolAddress(&p_h,  g_h);
    cudaGetSymbolAddress(&p_xh, g_xh);  cudaGetSymbolAddress(&p_xl, g_xl);
    cudaGetSymbolAddress(&p_hh, g_hh);  cudaGetSymbolAddress(&p_hl, g_hl);
    cudaGetSymbolAddress(&p_qh, g_qh);  cudaGetSymbolAddress(&p_ql, g_ql);
    cudaGetSymbolAddress(&p_w1h, g_w1h); cudaGetSymbolAddress(&p_w1l, g_w1l);
    cudaGetSymbolAddress(&p_w2h, g_w2h); cudaGetSymbolAddress(&p_w2l, g_w2l);
    cudaGetSymbolAddress(&p_bth, g_bth); cudaGetSymbolAddress(&p_btl, g_btl);

    float* hbuf = (float*)p_h;
    __nv_bfloat16 *xh = (__nv_bfloat16*)p_xh, *xl = (__nv_bfloat16*)p_xl;
    __nv_bfloat16 *hh = (__nv_bfloat16*)p_hh, *hl = (__nv_bfloat16*)p_hl;
    __nv_bfloat16 *qh = (__nv_bfloat16*)p_qh, *ql = (__nv_bfloat16*)p_ql;
    __nv_bfloat16 *w1h = (__nv_bfloat16*)p_w1h, *w1l = (__nv_bfloat16*)p_w1l;
    __nv_bfloat16 *w2h = (__nv_bfloat16*)p_w2h, *w2l = (__nv_bfloat16*)p_w2l;
    __nv_bfloat16 *bth = (__nv_bfloat16*)p_bth, *btl = (__nv_bfloat16*)p_btl;

    cudaFuncSetAttribute(gemm_mma<0>, cudaFuncAttributeMaxDynamicSharedMemorySize, SMEM_TOTAL);
    cudaFuncSetAttribute(gemm_mma<1>, cudaFuncAttributeMaxDynamicSharedMemorySize, SMEM_TOTAL);
    cudaFuncSetAttribute(gemm_mma<2>, cudaFuncAttributeMaxDynamicSharedMemorySize, SMEM_TOTAL);

    // hi/lo splits
    split_kernel<<<(B_ * D_ / 4) / 256, 256>>>(x,    mean,    xh,  xl,  D_ - 1, B_ * D_ / 4);
    split_kernel<<<(H_ * D_ / 4) / 256, 256>>>(W1,   nullptr, w1h, w1l, 0,      H_ * D_ / 4);
    split_kernel<<<(K_ * H_ / 4) / 256, 256>>>(W2,   nullptr, w2h, w2l, 0,      K_ * H_ / 4);
    split_kernel<<<(D_ * K_ / 4) / 256, 256>>>(beta, nullptr, bth, btl, 0,      D_ * K_ / 4);

    // GEMM1: h = (x-mean) @ W1^T + b1   [8192, 2048], K=4096
    gemm_mma<0><<<dim3(H_ / 128, B_ / 128), 256, SMEM_TOTAL>>>(
        xh, xl, w1h, w1l, b1, hbuf, nullptr, nullptr, nullptr, nullptr, H_, D_);

    // LayerNorm + ReLU -> bf16 split
    ln_relu_split<<<B_, 256>>>(hbuf, lnw, lnb, hh, hl);

    // GEMM2: q = h @ W2^T + b2   [8192, 512], K=2048  -> q0/q1/q2 + split
    gemm_mma<1><<<dim3(K_ / 128, B_ / 128), 256, SMEM_TOTAL>>>(
        hh, hl, w2h, w2l, b2, q0, q1, q2, qh, ql, K_, H_);

    // GEMM3: x_recon = sigmoid(q @ beta^T)   [8192, 4096], K=512
    gemm_mma<2><<<dim3(D_ / 128, B_ / 128), 256, SMEM_TOTAL>>>(
        qh, ql, bth, btl, nullptr, xr, nullptr, nullptr, nullptr, nullptr, D_, K_);
}

// round 5
// speedup vs baseline: 3.2535x; 1.3670x over previous
#include <cuda_runtime.h>
#include <cuda_fp16.h>
#include <cstdint>

#define B_ 8192
#define D_ 4096
#define H_ 2048
#define K_ 512
#define LN_EPS 1e-5f

// ---------------------------------------------------------------------------
// Scratch (device globals; runtime allocation forbidden)
// Activations: fp16 hi/lo split (exact to ~2^-21).
// Weights: single fp16 (rounded, 2^-11) -- the 2-product scheme's error source.
// ---------------------------------------------------------------------------
__device__ __align__(256) float  g_h  [(size_t)B_ * H_];
__device__ __align__(256) __half g_xh [(size_t)B_ * D_];
__device__ __align__(256) __half g_xl [(size_t)B_ * D_];
__device__ __align__(256) __half g_hh [(size_t)B_ * H_];
__device__ __align__(256) __half g_hl [(size_t)B_ * H_];
__device__ __align__(256) __half g_qh [(size_t)B_ * K_];
__device__ __align__(256) __half g_ql [(size_t)B_ * K_];
__device__ __align__(256) __half g_w1 [(size_t)H_ * D_];
__device__ __align__(256) __half g_w2 [(size_t)K_ * H_];
__device__ __align__(256) __half g_bt [(size_t)D_ * K_];

// ---------------------------------------------------------------------------
// Low-level helpers (base sm_103-legal: cp.async / ldmatrix / mma.sync)
// ---------------------------------------------------------------------------
__device__ __forceinline__ uint32_t smem_u32(const void* p) {
    uint32_t a;
    asm("{ .reg .u64 t; cvta.to.shared.u64 t, %1; cvt.u32.u64 %0, t; }"
        : "=r"(a) : "l"(p));
    return a;
}

__device__ __forceinline__ void cpa16(uint32_t dst, const void* src) {
    asm volatile("cp.async.cg.shared.global [%0], [%1], 16;"
                 :: "r"(dst), "l"(src) : "memory");
}
#define CP_COMMIT() asm volatile("cp.async.commit_group;" ::: "memory")
#define CP_WAIT2()  asm volatile("cp.async.wait_group 2;" ::: "memory")

#define LDM_X4(r0, r1, r2, r3, addr)                                          \
    asm volatile("ldmatrix.sync.aligned.m8n8.x4.shared.b16 {%0,%1,%2,%3}, [%4];" \
                 : "=r"(r0), "=r"(r1), "=r"(r2), "=r"(r3) : "r"(addr))

__device__ __forceinline__ void mma_f16(float* c, const uint32_t* a,
                                        uint32_t b0, uint32_t b1) {
    asm volatile(
        "mma.sync.aligned.m16n8k16.row.col.f32.f16.f16.f32 "
        "{%0,%1,%2,%3}, {%4,%5,%6,%7}, {%8,%9}, {%0,%1,%2,%3};"
        : "+f"(c[0]), "+f"(c[1]), "+f"(c[2]), "+f"(c[3])
        : "r"(a[0]), "r"(a[1]), "r"(a[2]), "r"(a[3]), "r"(b0), "r"(b1));
}

// ---------------------------------------------------------------------------
// SMEM per stage: K-chunk 64 fp16 (128B/row), rows padded to 144B
// (bank stride 36 mod 32 = 4 -> conflict-free ldmatrix).
//   Ah[128][72] @ 0       (18432 B)
//   Al[128][72] @ 18432
//   Bw[128][72] @ 36864
// Stage stride 55296 B, 3 stages = 165888 B dynamic SMEM.
// ---------------------------------------------------------------------------
#define ROWB   144
#define AH_OFF 0
#define AL_OFF 18432
#define BW_OFF 36864
#define STG    55296
#define SMEM_TOTAL (3 * STG)

__device__ __forceinline__ void load_stage(uint32_t stb,
    const __half* __restrict__ Ah, const __half* __restrict__ Al,
    const __half* __restrict__ Bw,
    int m0, int n0, int k0, int K, int tid)
{
#pragma unroll
    for (int i = 0; i < 4; ++i) {
        const int idx = tid + i * 256;
        const int r = idx >> 3;            // 0..127
        const int c = idx & 7;             // 16B chunk 0..7
        const size_t ga = (size_t)(m0 + r) * K + k0 + c * 8;
        const size_t gb = (size_t)(n0 + r) * K + k0 + c * 8;
        const uint32_t so = (uint32_t)(r * ROWB + c * 16);
        cpa16(stb + AH_OFF + so, Ah + ga);
        cpa16(stb + AL_OFF + so, Al + ga);
        cpa16(stb + BW_OFF + so, Bw + gb);
    }
}

// ---------------------------------------------------------------------------
// fp16 2-product tensor-core GEMM: C[128,128] CTA tile.
// A[M,K] activations as fp16 hi/lo; B[N,K] weights as fp16.
// D = Ah*Bw + Al*Bw  (fp32 accum, m16n8k16 HMMA). 8 warps, warp tile 32x64.
//   EPI 0: +bias -> C0
//   EPI 1: +bias -> C0,C1,C2 + fp16 split -> Oh/Ol
//   EPI 2: sigmoid -> C0
// ---------------------------------------------------------------------------
template<int EPI>
__global__ void __launch_bounds__(256, 1)
gemm_mma(const __half* __restrict__ Ah, const __half* __restrict__ Al,
         const __half* __restrict__ Bw,
         const float* __restrict__ bias,
         float* __restrict__ C0, float* __restrict__ C1, float* __restrict__ C2,
         __half* __restrict__ Oh, __half* __restrict__ Ol,
         int N, int K)
{
    extern __shared__ char smem[];
    const uint32_t sb = smem_u32(smem);

    const int tid  = threadIdx.x;
    const int lane = tid & 31;
    const int wid  = tid >> 5;
    const int wm   = wid & 3;        // 32-row slab
    const int wn   = wid >> 2;       // 64-col slab
    const int m0 = blockIdx.y * 128;
    const int n0 = blockIdx.x * 128;
    const int NC = K >> 6;

    const int lrow  = lane & 15;
    const int lcolb = ((lane >> 4) << 4);   // 0 or 16 bytes

    float acc[2][8][4];
#pragma unroll
    for (int m = 0; m < 2; ++m)
#pragma unroll
        for (int n = 0; n < 8; ++n)
#pragma unroll
            for (int j = 0; j < 4; ++j) acc[m][n][j] = 0.f;

    load_stage(sb,       Ah, Al, Bw, m0, n0, 0,  K, tid); CP_COMMIT();
    load_stage(sb + STG, Ah, Al, Bw, m0, n0, 64, K, tid); CP_COMMIT();

    uint32_t stg_idx = 0;
    for (int c = 0; c < NC; ++c) {
        if (c + 2 < NC) {
            uint32_t ls = stg_idx + 2; if (ls >= 3) ls -= 3;
            load_stage(sb + ls * STG, Ah, Al, Bw, m0, n0, (c + 2) << 6, K, tid);
        }
        CP_COMMIT();
        CP_WAIT2();
        __syncthreads();

        const uint32_t stb = sb + stg_idx * STG;
        const uint32_t abase = stb + (wm * 32 + lrow) * ROWB + lcolb;
        const uint32_t bbase = stb + BW_OFF + (wn * 64 + lrow) * ROWB + lcolb;

#pragma unroll
        for (int kk = 0; kk < 4; ++kk) {
            const uint32_t ko = kk * 32;   // 16 elems = 32 bytes
            uint32_t ah[2][4], al[2][4], bw[4][4];
#pragma unroll
            for (int m = 0; m < 2; ++m) {
                const uint32_t ao = abase + m * 16 * ROWB + ko;
                LDM_X4(ah[m][0], ah[m][1], ah[m][2], ah[m][3], ao + AH_OFF);
                LDM_X4(al[m][0], al[m][1], al[m][2], al[m][3], ao + AL_OFF);
            }
#pragma unroll
            for (int nt = 0; nt < 4; ++nt) {
                const uint32_t bo = bbase + nt * 16 * ROWB + ko;
                LDM_X4(bw[nt][0], bw[nt][1], bw[nt][2], bw[nt][3], bo);
            }
#pragma unroll
            for (int m = 0; m < 2; ++m)
#pragma unroll
                for (int nt = 0; nt < 4; ++nt) {
                    mma_f16(acc[m][2 * nt],     ah[m], bw[nt][0], bw[nt][2]);
                    mma_f16(acc[m][2 * nt + 1], ah[m], bw[nt][1], bw[nt][3]);
                    mma_f16(acc[m][2 * nt],     al[m], bw[nt][0], bw[nt][2]);
                    mma_f16(acc[m][2 * nt + 1], al[m], bw[nt][1], bw[nt][3]);
                }
        }
        __syncthreads();
        ++stg_idx; if (stg_idx == 3) stg_idx = 0;
    }

    // ------------------------------ epilogue ------------------------------
    const int rbase = m0 + wm * 32 + (lane >> 2);
    const int cbase = n0 + wn * 64 + 2 * (lane & 3);
#pragma unroll
    for (int m = 0; m < 2; ++m) {
        const int row = rbase + m * 16;
#pragma unroll
        for (int n = 0; n < 8; ++n) {
            const int col = cbase + n * 8;
            float v[4] = {acc[m][n][0], acc[m][n][1], acc[m][n][2], acc[m][n][3]};
            if (EPI == 0 || EPI == 1) {
                const float bb0 = bias[col], bb1 = bias[col + 1];
                v[0] += bb0; v[1] += bb1; v[2] += bb0; v[3] += bb1;
            }
            if (EPI == 2) {
#pragma unroll
                for (int j = 0; j < 4; ++j) v[j] = 1.f / (1.f + __expf(-v[j]));
            }
            const size_t o0 = (size_t)row * N + col;
            const size_t o1 = (size_t)(row + 8) * N + col;
            *reinterpret_cast<float2*>(C0 + o0) = make_float2(v[0], v[1]);
            *reinterpret_cast<float2*>(C0 + o1) = make_float2(v[2], v[3]);
            if (EPI == 1) {
                *reinterpret_cast<float2*>(C1 + o0) = make_float2(v[0], v[1]);
                *reinterpret_cast<float2*>(C1 + o1) = make_float2(v[2], v[3]);
                *reinterpret_cast<float2*>(C2 + o0) = make_float2(v[0], v[1]);
                *reinterpret_cast<float2*>(C2 + o1) = make_float2(v[2], v[3]);
                const size_t oo[4] = {o0, o0 + 1, o1, o1 + 1};
#pragma unroll
                for (int j = 0; j < 4; ++j) {
                    __half hv = __float2half(v[j]);
                    Oh[oo[j]] = hv;
                    Ol[oo[j]] = __float2half(v[j] - __half2float(hv));
                }
            }
        }
    }
}

// ---------------------------------------------------------------------------
// fp32 -> fp16 hi/lo split (lo may be null -> weights: single rounded fp16).
// Optional periodic mean subtraction (for x).
// ---------------------------------------------------------------------------
__global__ void __launch_bounds__(256)
split_kernel(const float* __restrict__ src, const float* __restrict__ mean,
             __half* __restrict__ hi, __half* __restrict__ lo,
             int dmask, int n4)
{
    int i = blockIdx.x * 256 + threadIdx.x;
    if (i >= n4) return;
    float4 v = reinterpret_cast<const float4*>(src)[i];
    int e = i * 4;
    if (mean) {
        v.x -= mean[(e + 0) & dmask]; v.y -= mean[(e + 1) & dmask];
        v.z -= mean[(e + 2) & dmask]; v.w -= mean[(e + 3) & dmask];
    }
    float a[4] = {v.x, v.y, v.z, v.w};
#pragma unroll
    for (int j = 0; j < 4; ++j) {
        __half h = __float2half(a[j]);
        hi[e + j] = h;
        if (lo) lo[e + j] = __float2half(a[j] - __half2float(h));
    }
}

// ---------------------------------------------------------------------------
// LayerNorm + ReLU over H, fp32 in -> fp16 hi/lo out
// ---------------------------------------------------------------------------
__global__ void __launch_bounds__(256)
ln_relu_split(const float* __restrict__ h, const float* __restrict__ w,
              const float* __restrict__ b,
              __half* __restrict__ oh, __half* __restrict__ ol)
{
    const int row = blockIdx.x;
    const int tid = threadIdx.x;
    const float4* hr = reinterpret_cast<const float4*>(h + (size_t)row * H_);

    float4 v0 = hr[tid];
    float4 v1 = hr[tid + 256];

    float s  = v0.x + v0.y + v0.z + v0.w + v1.x + v1.y + v1.z + v1.w;
    float sq = v0.x*v0.x + v0.y*v0.y + v0.z*v0.z + v0.w*v0.w
             + v1.x*v1.x + v1.y*v1.y + v1.z*v1.z + v1.w*v1.w;
#pragma unroll
    for (int o = 16; o; o >>= 1) {
        s  += __shfl_xor_sync(0xffffffffu, s,  o);
        sq += __shfl_xor_sync(0xffffffffu, sq, o);
    }
    __shared__ float red[16];
    const int wd = tid >> 5, lane = tid & 31;
    if (lane == 0) { red[wd] = s; red[8 + wd] = sq; }
    __syncthreads();
    float ts = 0.f, tq = 0.f;
#pragma unroll
    for (int i = 0; i < 8; ++i) { ts += red[i]; tq += red[8 + i]; }

    const float mu  = ts * (1.f / H_);
    const float var = tq * (1.f / H_) - mu * mu;
    const float rr  = rsqrtf(var + LN_EPS);

    const float4* w4 = reinterpret_cast<const float4*>(w);
    const float4* b4 = reinterpret_cast<const float4*>(b);
    const float4 w0 = w4[tid], w1 = w4[tid + 256];
    const float4 b0 = b4[tid], b1 = b4[tid + 256];

    float out[8];
    out[0] = fmaxf((v0.x - mu) * rr * w0.x + b0.x, 0.f);
    out[1] = fmaxf((v0.y - mu) * rr * w0.y + b0.y, 0.f);
    out[2] = fmaxf((v0.z - mu) * rr * w0.z + b0.z, 0.f);
    out[3] = fmaxf((v0.w - mu) * rr * w0.w + b0.w, 0.f);
    out[4] = fmaxf((v1.x - mu) * rr * w1.x + b1.x, 0.f);
    out[5] = fmaxf((v1.y - mu) * rr * w1.y + b1.y, 0.f);
    out[6] = fmaxf((v1.z - mu) * rr * w1.z + b1.z, 0.f);
    out[7] = fmaxf((v1.w - mu) * rr * w1.w + b1.w, 0.f);

    const size_t base0 = (size_t)row * H_ + (size_t)tid * 4;
    const size_t base1 = base0 + 1024;
#pragma unroll
    for (int j = 0; j < 4; ++j) {
        __half hv = __float2half(out[j]);
        oh[base0 + j] = hv;
        ol[base0 + j] = __float2half(out[j] - __half2float(hv));
        __half hv2 = __float2half(out[4 + j]);
        oh[base1 + j] = hv2;
        ol[base1 + j] = __float2half(out[4 + j] - __half2float(hv2));
    }
}

// ---------------------------------------------------------------------------
// kernel_launch  (GEMM1 moved to app-launch #3 so ncu's -s 5 captures it)
// ---------------------------------------------------------------------------
extern "C" void kernel_launch(void* const* d_in, const int* in_sizes, int n_in,
                              void* d_out, int out_size)
{
    const float* x    = (const float*)d_in[0];
    const float* beta = (const float*)d_in[1];
    const float* mean = (const float*)d_in[2];
    const float* W1   = (const float*)d_in[3];
    const float* b1   = (const float*)d_in[4];
    const float* lnw  = (const float*)d_in[5];
    const float* lnb  = (const float*)d_in[6];
    const float* W2   = (const float*)d_in[7];
    const float* b2   = (const float*)d_in[8];

    float* out = (float*)d_out;
    float* q0 = out;                        // [B, K]
    float* xr = out + (size_t)B_ * K_;      // [B, D]
    float* q1 = xr + (size_t)B_ * D_;       // [B, K]
    float* q2 = q1 + (size_t)B_ * K_;       // [B, K]

    void *p_h, *p_xh, *p_xl, *p_hh, *p_hl, *p_qh, *p_ql, *p_w1, *p_w2, *p_bt;
    cudaGetSymbolAddress(&p_h,  g_h);
    cudaGetSymbolAddress(&p_xh, g_xh);  cudaGetSymbolAddress(&p_xl, g_xl);
    cudaGetSymbolAddress(&p_hh, g_hh);  cudaGetSymbolAddress(&p_hl, g_hl);
    cudaGetSymbolAddress(&p_qh, g_qh);  cudaGetSymbolAddress(&p_ql, g_ql);
    cudaGetSymbolAddress(&p_w1, g_w1);
    cudaGetSymbolAddress(&p_w2, g_w2);
    cudaGetSymbolAddress(&p_bt, g_bt);

    float* hbuf = (float*)p_h;
    __half *xh = (__half*)p_xh, *xl = (__half*)p_xl;
    __half *hh = (__half*)p_hh, *hl = (__half*)p_hl;
    __half *qh = (__half*)p_qh, *ql = (__half*)p_ql;
    __half *w1 = (__half*)p_w1, *w2 = (__half*)p_w2, *bt = (__half*)p_bt;

    cudaFuncSetAttribute(gemm_mma<0>, cudaFuncAttributeMaxDynamicSharedMemorySize, SMEM_TOTAL);
    cudaFuncSetAttribute(gemm_mma<1>, cudaFuncAttributeMaxDynamicSharedMemorySize, SMEM_TOTAL);
    cudaFuncSetAttribute(gemm_mma<2>, cudaFuncAttributeMaxDynamicSharedMemorySize, SMEM_TOTAL);

    // #1: x split (hi/lo, with mean subtraction)
    split_kernel<<<(B_ * D_ / 4) / 256, 256>>>(x, mean, xh, xl, D_ - 1, B_ * D_ / 4);
    // #2: W1 round to fp16
    split_kernel<<<(H_ * D_ / 4) / 256, 256>>>(W1, nullptr, w1, nullptr, 0, H_ * D_ / 4);

    // #3: GEMM1: h = (x-mean) @ W1^T + b1   [8192, 2048], K=4096
    gemm_mma<0><<<dim3(H_ / 128, B_ / 128), 256, SMEM_TOTAL>>>(
        xh, xl, w1, b1, hbuf, nullptr, nullptr, nullptr, nullptr, H_, D_);

    // #4: W2 round; #5: beta round (only needed later)
    split_kernel<<<(K_ * H_ / 4) / 256, 256>>>(W2,   nullptr, w2, nullptr, 0, K_ * H_ / 4);
    split_kernel<<<(D_ * K_ / 4) / 256, 256>>>(beta, nullptr, bt, nullptr, 0, D_ * K_ / 4);

    // #6: LayerNorm + ReLU -> fp16 hi/lo
    ln_relu_split<<<B_, 256>>>(hbuf, lnw, lnb, hh, hl);

    // #7: GEMM2: q = h @ W2^T + b2   [8192, 512], K=2048 -> q0/q1/q2 + split
    gemm_mma<1><<<dim3(K_ / 128, B_ / 128), 256, SMEM_TOTAL>>>(
        hh, hl, w2, b2, q0, q1, q2, qh, ql, K_, H_);

    // #8: GEMM3: x_recon = sigmoid(q @ beta^T)   [8192, 4096], K=512
    gemm_mma<2><<<dim3(D_ / 128, B_ / 128), 256, SMEM_TOTAL>>>(
        qh, ql, bt, nullptr, xr, nullptr, nullptr, nullptr, nullptr, D_, K_);
}

// round 6
// speedup vs baseline: 6.6712x; 2.0505x over previous
#include <cuda_runtime.h>
#include <cuda_fp16.h>
#include <cstdint>

#define B_ 8192
#define D_ 4096
#define H_ 2048
#define K_ 512
#define LN_EPS 1e-5f

// ---------------------------------------------------------------------------
// Scratch (device globals; runtime allocation forbidden)
// Pure fp16 operands everywhere; fp32 accumulate in the MMAs.
// ---------------------------------------------------------------------------
__device__ __align__(256) float  g_h  [(size_t)B_ * H_];   // fp32 hidden (pre-LN)
__device__ __align__(256) __half g_xh [(size_t)B_ * D_];   // (x - mean) fp16
__device__ __align__(256) __half g_hh [(size_t)B_ * H_];   // LN+ReLU(h) fp16
__device__ __align__(256) __half g_qh [(size_t)B_ * K_];   // q_logits fp16
__device__ __align__(256) __half g_w1 [(size_t)H_ * D_];
__device__ __align__(256) __half g_w2 [(size_t)K_ * H_];
__device__ __align__(256) __half g_bt [(size_t)D_ * K_];

// ---------------------------------------------------------------------------
// Low-level helpers (base sm_103-legal: cp.async / ldmatrix / mma.sync)
// ---------------------------------------------------------------------------
__device__ __forceinline__ uint32_t smem_u32(const void* p) {
    uint32_t a;
    asm("{ .reg .u64 t; cvta.to.shared.u64 t, %1; cvt.u32.u64 %0, t; }"
        : "=r"(a) : "l"(p));
    return a;
}

__device__ __forceinline__ void cpa16(uint32_t dst, const void* src) {
    asm volatile("cp.async.cg.shared.global [%0], [%1], 16;"
                 :: "r"(dst), "l"(src) : "memory");
}
#define CP_COMMIT() asm volatile("cp.async.commit_group;" ::: "memory")
#define CP_WAIT2()  asm volatile("cp.async.wait_group 2;" ::: "memory")

#define LDM_X4(r0, r1, r2, r3, addr)                                          \
    asm volatile("ldmatrix.sync.aligned.m8n8.x4.shared.b16 {%0,%1,%2,%3}, [%4];" \
                 : "=r"(r0), "=r"(r1), "=r"(r2), "=r"(r3) : "r"(addr))

__device__ __forceinline__ void mma_f16(float* c, const uint32_t* a,
                                        uint32_t b0, uint32_t b1) {
    asm volatile(
        "mma.sync.aligned.m16n8k16.row.col.f32.f16.f16.f32 "
        "{%0,%1,%2,%3}, {%4,%5,%6,%7}, {%8,%9}, {%0,%1,%2,%3};"
        : "+f"(c[0]), "+f"(c[1]), "+f"(c[2]), "+f"(c[3])
        : "r"(a[0]), "r"(a[1]), "r"(a[2]), "r"(a[3]), "r"(b0), "r"(b1));
}

// ---------------------------------------------------------------------------
// SMEM per stage: K-chunk 64 fp16 (128B/row), rows padded to 144B
// (bank stride 36 mod 32 = 4 -> conflict-free ldmatrix).
//   A[128][72] @ 0      (18432 B)
//   B[128][72] @ 18432
// Stage 36864 B, 3 stages = 110592 B -> 2 CTAs/SM fit in the 227KB carveout.
// ---------------------------------------------------------------------------
#define ROWB   144
#define A_OFF  0
#define B_OFF  18432
#define STG    36864
#define SMEM_TOTAL (3 * STG)

__device__ __forceinline__ void load_stage(uint32_t stb,
    const __half* __restrict__ A, const __half* __restrict__ Bw,
    int m0, int n0, int k0, int K, int tid)
{
#pragma unroll
    for (int i = 0; i < 4; ++i) {
        const int idx = tid + i * 256;
        const int r = idx >> 3;            // 0..127
        const int c = idx & 7;             // 16B chunk 0..7
        const size_t ga = (size_t)(m0 + r) * K + k0 + c * 8;
        const size_t gb = (size_t)(n0 + r) * K + k0 + c * 8;
        const uint32_t so = (uint32_t)(r * ROWB + c * 16);
        cpa16(stb + A_OFF + so, A + ga);
        cpa16(stb + B_OFF + so, Bw + gb);
    }
}

// ---------------------------------------------------------------------------
// Pure fp16 tensor-core GEMM: C[128,128] CTA tile, fp32 accum.
// A[M,K], B[N,K] row-major fp16. 8 warps, warp tile 32x64, m16n8k16.
//   EPI 0: +bias -> C0 (fp32)
//   EPI 1: +bias -> C0,C1,C2 (fp32) + fp16 round -> Oh
//   EPI 2: sigmoid -> C0
// ---------------------------------------------------------------------------
template<int EPI>
__global__ void __launch_bounds__(256, 2)
gemm_mma(const __half* __restrict__ A, const __half* __restrict__ Bw,
         const float* __restrict__ bias,
         float* __restrict__ C0, float* __restrict__ C1, float* __restrict__ C2,
         __half* __restrict__ Oh,
         int N, int K)
{
    extern __shared__ char smem[];
    const uint32_t sb = smem_u32(smem);

    const int tid  = threadIdx.x;
    const int lane = tid & 31;
    const int wid  = tid >> 5;
    const int wm   = wid & 3;        // 32-row slab
    const int wn   = wid >> 2;       // 64-col slab
    const int m0 = blockIdx.y * 128;
    const int n0 = blockIdx.x * 128;
    const int NC = K >> 6;

    const int lrow  = lane & 15;
    const int lcolb = ((lane >> 4) << 4);   // 0 or 16 bytes

    float acc[2][8][4];
#pragma unroll
    for (int m = 0; m < 2; ++m)
#pragma unroll
        for (int n = 0; n < 8; ++n)
#pragma unroll
            for (int j = 0; j < 4; ++j) acc[m][n][j] = 0.f;

    load_stage(sb,       A, Bw, m0, n0, 0,  K, tid); CP_COMMIT();
    load_stage(sb + STG, A, Bw, m0, n0, 64, K, tid); CP_COMMIT();

    uint32_t stg_idx = 0;
    for (int c = 0; c < NC; ++c) {
        if (c + 2 < NC) {
            uint32_t ls = stg_idx + 2; if (ls >= 3) ls -= 3;
            load_stage(sb + ls * STG, A, Bw, m0, n0, (c + 2) << 6, K, tid);
        }
        CP_COMMIT();
        CP_WAIT2();
        __syncthreads();

        const uint32_t stb = sb + stg_idx * STG;
        const uint32_t abase = stb + A_OFF + (wm * 32 + lrow) * ROWB + lcolb;
        const uint32_t bbase = stb + B_OFF + (wn * 64 + lrow) * ROWB + lcolb;

#pragma unroll
        for (int kk = 0; kk < 4; ++kk) {
            const uint32_t ko = kk * 32;   // 16 elems = 32 bytes
            uint32_t a[2][4], b[4][4];
#pragma unroll
            for (int m = 0; m < 2; ++m) {
                const uint32_t ao = abase + m * 16 * ROWB + ko;
                LDM_X4(a[m][0], a[m][1], a[m][2], a[m][3], ao);
            }
#pragma unroll
            for (int nt = 0; nt < 4; ++nt) {
                const uint32_t bo = bbase + nt * 16 * ROWB + ko;
                LDM_X4(b[nt][0], b[nt][1], b[nt][2], b[nt][3], bo);
            }
#pragma unroll
            for (int m = 0; m < 2; ++m)
#pragma unroll
                for (int nt = 0; nt < 4; ++nt) {
                    mma_f16(acc[m][2 * nt],     a[m], b[nt][0], b[nt][2]);
                    mma_f16(acc[m][2 * nt + 1], a[m], b[nt][1], b[nt][3]);
                }
        }
        __syncthreads();
        ++stg_idx; if (stg_idx == 3) stg_idx = 0;
    }

    // ------------------------------ epilogue ------------------------------
    const int rbase = m0 + wm * 32 + (lane >> 2);
    const int cbase = n0 + wn * 64 + 2 * (lane & 3);
#pragma unroll
    for (int m = 0; m < 2; ++m) {
        const int row = rbase + m * 16;
#pragma unroll
        for (int n = 0; n < 8; ++n) {
            const int col = cbase + n * 8;
            float v[4] = {acc[m][n][0], acc[m][n][1], acc[m][n][2], acc[m][n][3]};
            if (EPI == 0 || EPI == 1) {
                const float bb0 = bias[col], bb1 = bias[col + 1];
                v[0] += bb0; v[1] += bb1; v[2] += bb0; v[3] += bb1;
            }
            if (EPI == 2) {
#pragma unroll
                for (int j = 0; j < 4; ++j) v[j] = 1.f / (1.f + __expf(-v[j]));
            }
            const size_t o0 = (size_t)row * N + col;
            const size_t o1 = (size_t)(row + 8) * N + col;
            *reinterpret_cast<float2*>(C0 + o0) = make_float2(v[0], v[1]);
            *reinterpret_cast<float2*>(C0 + o1) = make_float2(v[2], v[3]);
            if (EPI == 1) {
                *reinterpret_cast<float2*>(C1 + o0) = make_float2(v[0], v[1]);
                *reinterpret_cast<float2*>(C1 + o1) = make_float2(v[2], v[3]);
                *reinterpret_cast<float2*>(C2 + o0) = make_float2(v[0], v[1]);
                *reinterpret_cast<float2*>(C2 + o1) = make_float2(v[2], v[3]);
                Oh[o0]     = __float2half(v[0]);
                Oh[o0 + 1] = __float2half(v[1]);
                Oh[o1]     = __float2half(v[2]);
                Oh[o1 + 1] = __float2half(v[3]);
            }
        }
    }
}

// ---------------------------------------------------------------------------
// fp32 -> fp16 round (optional periodic mean subtraction, for x)
// ---------------------------------------------------------------------------
__global__ void __launch_bounds__(256)
cvt_kernel(const float* __restrict__ src, const float* __restrict__ mean,
           __half* __restrict__ hi, int dmask, int n4)
{
    int i = blockIdx.x * 256 + threadIdx.x;
    if (i >= n4) return;
    float4 v = reinterpret_cast<const float4*>(src)[i];
    int e = i * 4;
    if (mean) {
        v.x -= mean[(e + 0) & dmask]; v.y -= mean[(e + 1) & dmask];
        v.z -= mean[(e + 2) & dmask]; v.w -= mean[(e + 3) & dmask];
    }
    __half2 h01 = __floats2half2_rn(v.x, v.y);
    __half2 h23 = __floats2half2_rn(v.z, v.w);
    *reinterpret_cast<__half2*>(hi + e)     = h01;
    *reinterpret_cast<__half2*>(hi + e + 2) = h23;
}

// ---------------------------------------------------------------------------
// LayerNorm + ReLU over H, fp32 in -> fp16 out
// ---------------------------------------------------------------------------
__global__ void __launch_bounds__(256)
ln_relu(const float* __restrict__ h, const float* __restrict__ w,
        const float* __restrict__ b, __half* __restrict__ oh)
{
    const int row = blockIdx.x;
    const int tid = threadIdx.x;
    const float4* hr = reinterpret_cast<const float4*>(h + (size_t)row * H_);

    float4 v0 = hr[tid];
    float4 v1 = hr[tid + 256];

    float s  = v0.x + v0.y + v0.z + v0.w + v1.x + v1.y + v1.z + v1.w;
    float sq = v0.x*v0.x + v0.y*v0.y + v0.z*v0.z + v0.w*v0.w
             + v1.x*v1.x + v1.y*v1.y + v1.z*v1.z + v1.w*v1.w;
#pragma unroll
    for (int o = 16; o; o >>= 1) {
        s  += __shfl_xor_sync(0xffffffffu, s,  o);
        sq += __shfl_xor_sync(0xffffffffu, sq, o);
    }
    __shared__ float red[16];
    const int wd = tid >> 5, lane = tid & 31;
    if (lane == 0) { red[wd] = s; red[8 + wd] = sq; }
    __syncthreads();
    float ts = 0.f, tq = 0.f;
#pragma unroll
    for (int i = 0; i < 8; ++i) { ts += red[i]; tq += red[8 + i]; }

    const float mu  = ts * (1.f / H_);
    const float var = tq * (1.f / H_) - mu * mu;
    const float rr  = rsqrtf(var + LN_EPS);

    const float4* w4 = reinterpret_cast<const float4*>(w);
    const float4* b4 = reinterpret_cast<const float4*>(b);
    const float4 w0 = w4[tid], w1 = w4[tid + 256];
    const float4 b0 = b4[tid], b1 = b4[tid + 256];

    float o0 = fmaxf((v0.x - mu) * rr * w0.x + b0.x, 0.f);
    float o1 = fmaxf((v0.y - mu) * rr * w0.y + b0.y, 0.f);
    float o2 = fmaxf((v0.z - mu) * rr * w0.z + b0.z, 0.f);
    float o3 = fmaxf((v0.w - mu) * rr * w0.w + b0.w, 0.f);
    float o4 = fmaxf((v1.x - mu) * rr * w1.x + b1.x, 0.f);
    float o5 = fmaxf((v1.y - mu) * rr * w1.y + b1.y, 0.f);
    float o6 = fmaxf((v1.z - mu) * rr * w1.z + b1.z, 0.f);
    float o7 = fmaxf((v1.w - mu) * rr * w1.w + b1.w, 0.f);

    const size_t base0 = (size_t)row * H_ + (size_t)tid * 4;
    const size_t base1 = base0 + 1024;
    *reinterpret_cast<__half2*>(oh + base0)     = __floats2half2_rn(o0, o1);
    *reinterpret_cast<__half2*>(oh + base0 + 2) = __floats2half2_rn(o2, o3);
    *reinterpret_cast<__half2*>(oh + base1)     = __floats2half2_rn(o4, o5);
    *reinterpret_cast<__half2*>(oh + base1 + 2) = __floats2half2_rn(o6, o7);
}

// ---------------------------------------------------------------------------
// kernel_launch  (GEMM1 at app-launch #4 -- where ncu captured last round)
// ---------------------------------------------------------------------------
extern "C" void kernel_launch(void* const* d_in, const int* in_sizes, int n_in,
                              void* d_out, int out_size)
{
    const float* x    = (const float*)d_in[0];
    const float* beta = (const float*)d_in[1];
    const float* mean = (const float*)d_in[2];
    const float* W1   = (const float*)d_in[3];
    const float* b1   = (const float*)d_in[4];
    const float* lnw  = (const float*)d_in[5];
    const float* lnb  = (const float*)d_in[6];
    const float* W2   = (const float*)d_in[7];
    const float* b2   = (const float*)d_in[8];

    float* out = (float*)d_out;
    float* q0 = out;                        // [B, K]
    float* xr = out + (size_t)B_ * K_;      // [B, D]
    float* q1 = xr + (size_t)B_ * D_;       // [B, K]
    float* q2 = q1 + (size_t)B_ * K_;       // [B, K]

    void *p_h, *p_xh, *p_hh, *p_qh, *p_w1, *p_w2, *p_bt;
    cudaGetSymbolAddress(&p_h,  g_h);
    cudaGetSymbolAddress(&p_xh, g_xh);
    cudaGetSymbolAddress(&p_hh, g_hh);
    cudaGetSymbolAddress(&p_qh, g_qh);
    cudaGetSymbolAddress(&p_w1, g_w1);
    cudaGetSymbolAddress(&p_w2, g_w2);
    cudaGetSymbolAddress(&p_bt, g_bt);

    float* hbuf = (float*)p_h;
    __half *xh = (__half*)p_xh, *hh = (__half*)p_hh, *qh = (__half*)p_qh;
    __half *w1 = (__half*)p_w1, *w2 = (__half*)p_w2, *bt = (__half*)p_bt;

    cudaFuncSetAttribute(gemm_mma<0>, cudaFuncAttributeMaxDynamicSharedMemorySize, SMEM_TOTAL);
    cudaFuncSetAttribute(gemm_mma<1>, cudaFuncAttributeMaxDynamicSharedMemorySize, SMEM_TOTAL);
    cudaFuncSetAttribute(gemm_mma<2>, cudaFuncAttributeMaxDynamicSharedMemorySize, SMEM_TOTAL);

    // #1: x -> fp16 (with mean subtraction)
    cvt_kernel<<<(B_ * D_ / 4) / 256, 256>>>(x, mean, xh, D_ - 1, B_ * D_ / 4);
    // #2: W1 -> fp16
    cvt_kernel<<<(H_ * D_ / 4) / 256, 256>>>(W1, nullptr, w1, 0, H_ * D_ / 4);
    // #3: W2 -> fp16
    cvt_kernel<<<(K_ * H_ / 4) / 256, 256>>>(W2, nullptr, w2, 0, K_ * H_ / 4);

    // #4: GEMM1: h = (x-mean) @ W1^T + b1   [8192, 2048], K=4096
    gemm_mma<0><<<dim3(H_ / 128, B_ / 128), 256, SMEM_TOTAL>>>(
        xh, w1, b1, hbuf, nullptr, nullptr, nullptr, H_, D_);

    // #5: beta -> fp16
    cvt_kernel<<<(D_ * K_ / 4) / 256, 256>>>(beta, nullptr, bt, 0, D_ * K_ / 4);

    // #6: LayerNorm + ReLU -> fp16
    ln_relu<<<B_, 256>>>(hbuf, lnw, lnb, hh);

    // #7: GEMM2: q = h @ W2^T + b2   [8192, 512], K=2048 -> q0/q1/q2 + fp16 q
    gemm_mma<1><<<dim3(K_ / 128, B_ / 128), 256, SMEM_TOTAL>>>(
        hh, w2, b2, q0, q1, q2, qh, K_, H_);

    // #8: GEMM3: x_recon = sigmoid(q @ beta^T)   [8192, 4096], K=512
    gemm_mma<2><<<dim3(D_ / 128, B_ / 128), 256, SMEM_TOTAL>>>(
        qh, bt, nullptr, xr, nullptr, nullptr, nullptr, D_, K_);
}

// round 7
// speedup vs baseline: 6.6911x; 1.0030x over previous
#include <cuda_runtime.h>
#include <cuda_fp16.h>
#include <cstdint>

#define B_ 8192
#define D_ 4096
#define H_ 2048
#define K_ 512
#define LN_EPS 1e-5f

// ---------------------------------------------------------------------------
// Scratch (device globals; runtime allocation forbidden)
// ---------------------------------------------------------------------------
__device__ __align__(256) float  g_h  [(size_t)B_ * H_];   // fp32 hidden (pre-LN)
__device__ __align__(256) __half g_xh [(size_t)B_ * D_];   // (x - mean) fp16
__device__ __align__(256) __half g_hh [(size_t)B_ * H_];   // LN+ReLU(h) fp16
__device__ __align__(256) __half g_qh [(size_t)B_ * K_];   // q_logits fp16
__device__ __align__(256) __half g_w1 [(size_t)H_ * D_];
__device__ __align__(256) __half g_w2 [(size_t)K_ * H_];
__device__ __align__(256) __half g_bt [(size_t)D_ * K_];

// ---------------------------------------------------------------------------
// Low-level helpers
// ---------------------------------------------------------------------------
__device__ __forceinline__ uint32_t smem_u32(const void* p) {
    uint32_t a;
    asm("{ .reg .u64 t; cvta.to.shared.u64 t, %1; cvt.u32.u64 %0, t; }"
        : "=r"(a) : "l"(p));
    return a;
}

__device__ __forceinline__ void cpa16(uint32_t dst, const void* src) {
    asm volatile("cp.async.cg.shared.global [%0], [%1], 16;"
                 :: "r"(dst), "l"(src) : "memory");
}
#define CP_COMMIT() asm volatile("cp.async.commit_group;" ::: "memory")
#define CP_WAIT1()  asm volatile("cp.async.wait_group 1;" ::: "memory")
#define CP_WAIT0()  asm volatile("cp.async.wait_group 0;" ::: "memory")

#define LDM_X4(r0, r1, r2, r3, addr)                                          \
    asm volatile("ldmatrix.sync.aligned.m8n8.x4.shared.b16 {%0,%1,%2,%3}, [%4];" \
                 : "=r"(r0), "=r"(r1), "=r"(r2), "=r"(r3) : "r"(addr))

__device__ __forceinline__ void mma_f16(float* c, const uint32_t* a,
                                        uint32_t b0, uint32_t b1) {
    asm volatile(
        "mma.sync.aligned.m16n8k16.row.col.f32.f16.f16.f32 "
        "{%0,%1,%2,%3}, {%4,%5,%6,%7}, {%8,%9}, {%0,%1,%2,%3};"
        : "+f"(c[0]), "+f"(c[1]), "+f"(c[2]), "+f"(c[3])
        : "r"(a[0]), "r"(a[1]), "r"(a[2]), "r"(a[3]), "r"(b0), "r"(b1));
}

// ---------------------------------------------------------------------------
// SMEM per stage: K-chunk 64 fp16 (128B/row), rows padded to 144B
// (bank stride 36 mod 32 = 4 -> conflict-free ldmatrix).
//   A[128][72] @ 0      (18432 B)
//   B[128][72] @ 18432
// Stage 36864 B, 3 stages = 110592 B -> 2 CTAs/SM.
// ---------------------------------------------------------------------------
#define ROWB   144
#define A_OFF  0
#define B_OFF  18432
#define STG    36864
#define SMEM_TOTAL (3 * STG)

__device__ __forceinline__ void load_stage(uint32_t stb,
    const __half* __restrict__ A, const __half* __restrict__ Bw,
    int m0, int n0, int k0, int K, int tid)
{
#pragma unroll
    for (int i = 0; i < 4; ++i) {
        const int idx = tid + i * 256;
        const int r = idx >> 3;            // 0..127
        const int c = idx & 7;             // 16B chunk 0..7
        const size_t ga = (size_t)(m0 + r) * K + k0 + c * 8;
        const size_t gb = (size_t)(n0 + r) * K + k0 + c * 8;
        const uint32_t so = (uint32_t)(r * ROWB + c * 16);
        cpa16(stb + A_OFF + so, A + ga);
        cpa16(stb + B_OFF + so, Bw + gb);
    }
}

// ---------------------------------------------------------------------------
// Pure fp16 tensor-core GEMM, single-barrier 3-stage pipeline.
// C[128,128] CTA tile, 8 warps, warp tile 32x64, m16n8k16, fp32 accum.
//   EPI 0: +bias -> C0
//   EPI 1: +bias -> C0,C1,C2 + fp16 round -> Oh
//   EPI 2: sigmoid -> C0
// ---------------------------------------------------------------------------
template<int EPI>
__global__ void __launch_bounds__(256, 2)
gemm_mma(const __half* __restrict__ A, const __half* __restrict__ Bw,
         const float* __restrict__ bias,
         float* __restrict__ C0, float* __restrict__ C1, float* __restrict__ C2,
         __half* __restrict__ Oh,
         int N, int K)
{
    extern __shared__ char smem[];
    const uint32_t sb = smem_u32(smem);

    const int tid  = threadIdx.x;
    const int lane = tid & 31;
    const int wid  = tid >> 5;
    const int wm   = wid & 3;        // 32-row slab
    const int wn   = wid >> 2;       // 64-col slab
    const int m0 = blockIdx.y * 128;
    const int n0 = blockIdx.x * 128;
    const int NC = K >> 6;

    const int lrow  = lane & 15;
    const int lcolb = ((lane >> 4) << 4);   // 0 or 16 bytes

    float acc[2][8][4];
#pragma unroll
    for (int m = 0; m < 2; ++m)
#pragma unroll
        for (int n = 0; n < 8; ++n)
#pragma unroll
            for (int j = 0; j < 4; ++j) acc[m][n][j] = 0.f;

    // prologue: chunks 0,1 -> stages 0,1
    load_stage(sb,       A, Bw, m0, n0, 0,  K, tid); CP_COMMIT();
    load_stage(sb + STG, A, Bw, m0, n0, 64, K, tid); CP_COMMIT();

    uint32_t cur = 0;      // stage of chunk c
    for (int c = 0; c < NC; ++c) {
        // chunk c arrived? ({c, c+1} may be in flight; leave c+1 pending)
        if (c + 1 < NC) CP_WAIT1(); else CP_WAIT0();
        __syncthreads();   // single barrier: data visibility + WAR protection

        // prefetch chunk c+2 into stage (cur+2)%3 -- its last readers finished
        // before the barrier above (they read it as chunk c-1).
        if (c + 2 < NC) {
            uint32_t ls = cur + 2; if (ls >= 3) ls -= 3;
            load_stage(sb + ls * STG, A, Bw, m0, n0, (c + 2) << 6, K, tid);
            CP_COMMIT();
        }

        const uint32_t stb = sb + cur * STG;
        const uint32_t abase = stb + A_OFF + (wm * 32 + lrow) * ROWB + lcolb;
        const uint32_t bbase = stb + B_OFF + (wn * 64 + lrow) * ROWB + lcolb;

#pragma unroll
        for (int kk = 0; kk < 4; ++kk) {
            const uint32_t ko = kk * 32;   // 16 elems = 32 bytes
            uint32_t a[2][4], b[4][4];
#pragma unroll
            for (int m = 0; m < 2; ++m) {
                const uint32_t ao = abase + m * 16 * ROWB + ko;
                LDM_X4(a[m][0], a[m][1], a[m][2], a[m][3], ao);
            }
#pragma unroll
            for (int nt = 0; nt < 4; ++nt) {
                const uint32_t bo = bbase + nt * 16 * ROWB + ko;
                LDM_X4(b[nt][0], b[nt][1], b[nt][2], b[nt][3], bo);
            }
#pragma unroll
            for (int m = 0; m < 2; ++m)
#pragma unroll
                for (int nt = 0; nt < 4; ++nt) {
                    mma_f16(acc[m][2 * nt],     a[m], b[nt][0], b[nt][2]);
                    mma_f16(acc[m][2 * nt + 1], a[m], b[nt][1], b[nt][3]);
                }
        }
        ++cur; if (cur == 3) cur = 0;
    }

    // ------------------------------ epilogue ------------------------------
    const int rbase = m0 + wm * 32 + (lane >> 2);
    const int cbase = n0 + wn * 64 + 2 * (lane & 3);
#pragma unroll
    for (int m = 0; m < 2; ++m) {
        const int row = rbase + m * 16;
#pragma unroll
        for (int n = 0; n < 8; ++n) {
            const int col = cbase + n * 8;
            float v[4] = {acc[m][n][0], acc[m][n][1], acc[m][n][2], acc[m][n][3]};
            if (EPI == 0 || EPI == 1) {
                const float bb0 = bias[col], bb1 = bias[col + 1];
                v[0] += bb0; v[1] += bb1; v[2] += bb0; v[3] += bb1;
            }
            if (EPI == 2) {
#pragma unroll
                for (int j = 0; j < 4; ++j) v[j] = 1.f / (1.f + __expf(-v[j]));
            }
            const size_t o0 = (size_t)row * N + col;
            const size_t o1 = (size_t)(row + 8) * N + col;
            *reinterpret_cast<float2*>(C0 + o0) = make_float2(v[0], v[1]);
            *reinterpret_cast<float2*>(C0 + o1) = make_float2(v[2], v[3]);
            if (EPI == 1) {
                *reinterpret_cast<float2*>(C1 + o0) = make_float2(v[0], v[1]);
                *reinterpret_cast<float2*>(C1 + o1) = make_float2(v[2], v[3]);
                *reinterpret_cast<float2*>(C2 + o0) = make_float2(v[0], v[1]);
                *reinterpret_cast<float2*>(C2 + o1) = make_float2(v[2], v[3]);
                Oh[o0]     = __float2half(v[0]);
                Oh[o0 + 1] = __float2half(v[1]);
                Oh[o1]     = __float2half(v[2]);
                Oh[o1 + 1] = __float2half(v[3]);
            }
        }
    }
}

// ---------------------------------------------------------------------------
// fp32 -> fp16 round (optional periodic mean subtraction, for x)
// ---------------------------------------------------------------------------
__global__ void __launch_bounds__(256)
cvt_kernel(const float* __restrict__ src, const float* __restrict__ mean,
           __half* __restrict__ hi, int dmask, int n4)
{
    int i = blockIdx.x * 256 + threadIdx.x;
    if (i >= n4) return;
    float4 v = reinterpret_cast<const float4*>(src)[i];
    int e = i * 4;
    if (mean) {
        v.x -= mean[(e + 0) & dmask]; v.y -= mean[(e + 1) & dmask];
        v.z -= mean[(e + 2) & dmask]; v.w -= mean[(e + 3) & dmask];
    }
    *reinterpret_cast<__half2*>(hi + e)     = __floats2half2_rn(v.x, v.y);
    *reinterpret_cast<__half2*>(hi + e + 2) = __floats2half2_rn(v.z, v.w);
}

// ---------------------------------------------------------------------------
// LayerNorm + ReLU over H, fp32 in -> fp16 out
// ---------------------------------------------------------------------------
__global__ void __launch_bounds__(256)
ln_relu(const float* __restrict__ h, const float* __restrict__ w,
        const float* __restrict__ b, __half* __restrict__ oh)
{
    const int row = blockIdx.x;
    const int tid = threadIdx.x;
    const float4* hr = reinterpret_cast<const float4*>(h + (size_t)row * H_);

    float4 v0 = hr[tid];
    float4 v1 = hr[tid + 256];

    float s  = v0.x + v0.y + v0.z + v0.w + v1.x + v1.y + v1.z + v1.w;
    float sq = v0.x*v0.x + v0.y*v0.y + v0.z*v0.z + v0.w*v0.w
             + v1.x*v1.x + v1.y*v1.y + v1.z*v1.z + v1.w*v1.w;
#pragma unroll
    for (int o = 16; o; o >>= 1) {
        s  += __shfl_xor_sync(0xffffffffu, s,  o);
        sq += __shfl_xor_sync(0xffffffffu, sq, o);
    }
    __shared__ float red[16];
    const int wd = tid >> 5, lane = tid & 31;
    if (lane == 0) { red[wd] = s; red[8 + wd] = sq; }
    __syncthreads();
    float ts = 0.f, tq = 0.f;
#pragma unroll
    for (int i = 0; i < 8; ++i) { ts += red[i]; tq += red[8 + i]; }

    const float mu  = ts * (1.f / H_);
    const float var = tq * (1.f / H_) - mu * mu;
    const float rr  = rsqrtf(var + LN_EPS);

    const float4* w4 = reinterpret_cast<const float4*>(w);
    const float4* b4 = reinterpret_cast<const float4*>(b);
    const float4 w0 = w4[tid], w1 = w4[tid + 256];
    const float4 b0 = b4[tid], b1 = b4[tid + 256];

    float o0 = fmaxf((v0.x - mu) * rr * w0.x + b0.x, 0.f);
    float o1 = fmaxf((v0.y - mu) * rr * w0.y + b0.y, 0.f);
    float o2 = fmaxf((v0.z - mu) * rr * w0.z + b0.z, 0.f);
    float o3 = fmaxf((v0.w - mu) * rr * w0.w + b0.w, 0.f);
    float o4 = fmaxf((v1.x - mu) * rr * w1.x + b1.x, 0.f);
    float o5 = fmaxf((v1.y - mu) * rr * w1.y + b1.y, 0.f);
    float o6 = fmaxf((v1.z - mu) * rr * w1.z + b1.z, 0.f);
    float o7 = fmaxf((v1.w - mu) * rr * w1.w + b1.w, 0.f);

    const size_t base0 = (size_t)row * H_ + (size_t)tid * 4;
    const size_t base1 = base0 + 1024;
    *reinterpret_cast<__half2*>(oh + base0)     = __floats2half2_rn(o0, o1);
    *reinterpret_cast<__half2*>(oh + base0 + 2) = __floats2half2_rn(o2, o3);
    *reinterpret_cast<__half2*>(oh + base1)     = __floats2half2_rn(o4, o5);
    *reinterpret_cast<__half2*>(oh + base1 + 2) = __floats2half2_rn(o6, o7);
}

// ---------------------------------------------------------------------------
// kernel_launch  (GEMM1 at app-launch #4 -- the ncu capture slot)
// ---------------------------------------------------------------------------
extern "C" void kernel_launch(void* const* d_in, const int* in_sizes, int n_in,
                              void* d_out, int out_size)
{
    const float* x    = (const float*)d_in[0];
    const float* beta = (const float*)d_in[1];
    const float* mean = (const float*)d_in[2];
    const float* W1   = (const float*)d_in[3];
    const float* b1   = (const float*)d_in[4];
    const float* lnw  = (const float*)d_in[5];
    const float* lnb  = (const float*)d_in[6];
    const float* W2   = (const float*)d_in[7];
    const float* b2   = (const float*)d_in[8];

    float* out = (float*)d_out;
    float* q0 = out;                        // [B, K]
    float* xr = out + (size_t)B_ * K_;      // [B, D]
    float* q1 = xr + (size_t)B_ * D_;       // [B, K]
    float* q2 = q1 + (size_t)B_ * K_;       // [B, K]

    void *p_h, *p_xh, *p_hh, *p_qh, *p_w1, *p_w2, *p_bt;
    cudaGetSymbolAddress(&p_h,  g_h);
    cudaGetSymbolAddress(&p_xh, g_xh);
    cudaGetSymbolAddress(&p_hh, g_hh);
    cudaGetSymbolAddress(&p_qh, g_qh);
    cudaGetSymbolAddress(&p_w1, g_w1);
    cudaGetSymbolAddress(&p_w2, g_w2);
    cudaGetSymbolAddress(&p_bt, g_bt);

    float* hbuf = (float*)p_h;
    __half *xh = (__half*)p_xh, *hh = (__half*)p_hh, *qh = (__half*)p_qh;
    __half *w1 = (__half*)p_w1, *w2 = (__half*)p_w2, *bt = (__half*)p_bt;

    cudaFuncSetAttribute(gemm_mma<0>, cudaFuncAttributeMaxDynamicSharedMemorySize, SMEM_TOTAL);
    cudaFuncSetAttribute(gemm_mma<1>, cudaFuncAttributeMaxDynamicSharedMemorySize, SMEM_TOTAL);
    cudaFuncSetAttribute(gemm_mma<2>, cudaFuncAttributeMaxDynamicSharedMemorySize, SMEM_TOTAL);

    // #1: x -> fp16 (with mean subtraction)
    cvt_kernel<<<(B_ * D_ / 4) / 256, 256>>>(x, mean, xh, D_ - 1, B_ * D_ / 4);
    // #2: W1 -> fp16
    cvt_kernel<<<(H_ * D_ / 4) / 256, 256>>>(W1, nullptr, w1, 0, H_ * D_ / 4);
    // #3: W2 -> fp16
    cvt_kernel<<<(K_ * H_ / 4) / 256, 256>>>(W2, nullptr, w2, 0, K_ * H_ / 4);

    // #4: GEMM1: h = (x-mean) @ W1^T + b1   [8192, 2048], K=4096
    gemm_mma<0><<<dim3(H_ / 128, B_ / 128), 256, SMEM_TOTAL>>>(
        xh, w1, b1, hbuf, nullptr, nullptr, nullptr, H_, D_);

    // #5: beta -> fp16
    cvt_kernel<<<(D_ * K_ / 4) / 256, 256>>>(beta, nullptr, bt, 0, D_ * K_ / 4);

    // #6: LayerNorm + ReLU -> fp16
    ln_relu<<<B_, 256>>>(hbuf, lnw, lnb, hh);

    // #7: GEMM2: q = h @ W2^T + b2   [8192, 512], K=2048 -> q0/q1/q2 + fp16 q
    gemm_mma<1><<<dim3(K_ / 128, B_ / 128), 256, SMEM_TOTAL>>>(
        hh, w2, b2, q0, q1, q2, qh, K_, H_);

    // #8: GEMM3: x_recon = sigmoid(q @ beta^T)   [8192, 4096], K=512
    gemm_mma<2><<<dim3(D_ / 128, B_ / 128), 256, SMEM_TOTAL>>>(
        qh, bt, nullptr, xr, nullptr, nullptr, nullptr, D_, K_);
}